// round 4
// baseline (speedup 1.0000x reference)
#include <cuda_runtime.h>
#include <math.h>

#define BB   32
#define HH   56
#define WWID 56
#define CC   192
#define HEADS 6
#define HD   32
#define WS   7
#define SHIFT 3
#define HID  768
#define NTOK (BB*HH*WWID)          // 100352
#define NWIN (BB*8*8)              // 2048
#define NN   (WS*WS)               // 49

// -------- scratch (device globals; no allocations allowed) --------
__device__ float g_win [(size_t)NTOK * CC];      // LN1+shift+partition; reused for proj out
__device__ float g_qkv [(size_t)NTOK * 3 * CC];  // qkv
__device__ float g_attn[(size_t)NTOK * CC];      // attention out; reused for ln2 out
__device__ float g_res1[(size_t)NTOK * CC];      // x + attn branch
__device__ float g_hid [(size_t)NTOK * HID];     // fc1 out
__device__ float g_bias[HEADS * NN * NN];        // gathered rel-pos bias

// ----------------------------------------------------------------
// bias gather: g_bias[h][i][j] = table[rel_index[i*49+j]][h]
__global__ void bias_pre_kernel(const float* __restrict__ table,
                                const int* __restrict__ relidx) {
    int p = blockIdx.x * blockDim.x + threadIdx.x;
    if (p < NN * NN) {
        int idx = relidx[p];
        #pragma unroll
        for (int h = 0; h < HEADS; h++)
            g_bias[h * NN * NN + p] = table[idx * HEADS + h];
    }
}

// ----------------------------------------------------------------
// LN over C=192 + shift(-3,-3) + window partition. One block per output token.
__global__ void __launch_bounds__(192) ln_shift_win_kernel(
    const float* __restrict__ x, const float* __restrict__ g,
    const float* __restrict__ b) {
    int o = blockIdx.x;
    int win = o / NN, pos = o % NN;
    int bb = win >> 6, wi = (win >> 3) & 7, wj = win & 7;
    int i = pos / WS, j = pos % WS;
    int hs = (wi * WS + i + SHIFT) % HH;
    int ws2 = (wj * WS + j + SHIFT) % WWID;
    const float* row = x + ((size_t)(bb * HH + hs) * WWID + ws2) * CC;
    int c = threadIdx.x;
    float v = row[c];
    float s = v, s2 = v * v;
    #pragma unroll
    for (int off = 16; off; off >>= 1) {
        s  += __shfl_down_sync(0xffffffffu, s,  off);
        s2 += __shfl_down_sync(0xffffffffu, s2, off);
    }
    __shared__ float sh[12];
    if ((threadIdx.x & 31) == 0) { sh[threadIdx.x >> 5] = s; sh[6 + (threadIdx.x >> 5)] = s2; }
    __syncthreads();
    float ts = 0.f, ts2 = 0.f;
    #pragma unroll
    for (int w = 0; w < 6; w++) { ts += sh[w]; ts2 += sh[6 + w]; }
    float mu = ts * (1.0f / CC);
    float var = ts2 * (1.0f / CC) - mu * mu;
    float rs = rsqrtf(var + 1e-5f);
    g_win[(size_t)o * CC + c] = (v - mu) * rs * g[c] + b[c];
}

// ----------------------------------------------------------------
// window reverse + unshift + residual + LN2. One block per pixel token.
__global__ void __launch_bounds__(192) resid_ln2_kernel(
    const float* __restrict__ x, const float* __restrict__ g,
    const float* __restrict__ b) {
    int t = blockIdx.x;
    int bb = t / (HH * WWID); int rem = t % (HH * WWID);
    int h = rem / WWID, w = rem % WWID;
    int h2 = (h + HH - SHIFT) % HH, w2 = (w + WWID - SHIFT) % WWID;
    int o = ((bb * 64 + (h2 / WS) * 8 + (w2 / WS)) * NN + (h2 % WS) * WS + (w2 % WS));
    int c = threadIdx.x;
    float v = x[(size_t)t * CC + c] + g_win[(size_t)o * CC + c];
    g_res1[(size_t)t * CC + c] = v;
    float s = v, s2 = v * v;
    #pragma unroll
    for (int off = 16; off; off >>= 1) {
        s  += __shfl_down_sync(0xffffffffu, s,  off);
        s2 += __shfl_down_sync(0xffffffffu, s2, off);
    }
    __shared__ float sh[12];
    if ((threadIdx.x & 31) == 0) { sh[threadIdx.x >> 5] = s; sh[6 + (threadIdx.x >> 5)] = s2; }
    __syncthreads();
    float ts = 0.f, ts2 = 0.f;
    #pragma unroll
    for (int ww = 0; ww < 6; ww++) { ts += sh[ww]; ts2 += sh[6 + ww]; }
    float mu = ts * (1.0f / CC);
    float var = ts2 * (1.0f / CC) - mu * mu;
    float rs = rsqrtf(var + 1e-5f);
    g_attn[(size_t)t * CC + c] = (v - mu) * rs * g[c] + b[c];  // ln2 out (reuses g_attn)
}

// ----------------------------------------------------------------
// Generic NT GEMM: C[m,n] = sum_k A[m,k]*Bw[n,k] + bias[n]; EPI 0=bias, 1=+GELU, 2=+residual
// Assumes M%64==0, N%64==0, K%16==0.
#define BM 64
#define BN 64
#define BK 16
template<int EPI>
__global__ void __launch_bounds__(256) gemm_nt(
    const float* __restrict__ A, const float* __restrict__ Bw,
    const float* __restrict__ bias, const float* __restrict__ res,
    float* __restrict__ Cc, int M, int N, int K) {
    __shared__ float As[BK][BM];
    __shared__ float Bs[BK][BN];
    int t  = threadIdx.x;
    int m0 = blockIdx.y * BM;
    int n0 = blockIdx.x * BN;
    int tx = t & 15, ty = t >> 4;
    int lr = t & 63;          // row within tile
    int lk = (t >> 6) * 4;    // k offset (0,4,8,12)
    float acc[4][4] = {};
    for (int k0 = 0; k0 < K; k0 += BK) {
        float4 av = *(const float4*)(A  + (size_t)(m0 + lr) * K + k0 + lk);
        float4 bv = *(const float4*)(Bw + (size_t)(n0 + lr) * K + k0 + lk);
        As[lk + 0][lr] = av.x; As[lk + 1][lr] = av.y; As[lk + 2][lr] = av.z; As[lk + 3][lr] = av.w;
        Bs[lk + 0][lr] = bv.x; Bs[lk + 1][lr] = bv.y; Bs[lk + 2][lr] = bv.z; Bs[lk + 3][lr] = bv.w;
        __syncthreads();
        #pragma unroll
        for (int kk = 0; kk < BK; kk++) {
            float4 a = *(const float4*)&As[kk][ty * 4];
            float4 b = *(const float4*)&Bs[kk][tx * 4];
            float ar[4] = {a.x, a.y, a.z, a.w};
            float br[4] = {b.x, b.y, b.z, b.w};
            #pragma unroll
            for (int i = 0; i < 4; i++)
                #pragma unroll
                for (int j = 0; j < 4; j++)
                    acc[i][j] += ar[i] * br[j];
        }
        __syncthreads();
    }
    #pragma unroll
    for (int i = 0; i < 4; i++) {
        int m = m0 + ty * 4 + i;
        #pragma unroll
        for (int j = 0; j < 4; j++) {
            int n = n0 + tx * 4 + j;
            float c = acc[i][j] + bias[n];
            if (EPI == 1) c = 0.5f * c * (1.0f + erff(c * 0.7071067811865476f));
            if (EPI == 2) c += res[(size_t)m * N + n];
            Cc[(size_t)m * N + n] = c;
        }
    }
}

// ----------------------------------------------------------------
// Per-(window, head) attention: smem-resident q,k,v; fused bias+softmax.
__global__ void __launch_bounds__(128) attn_kernel() {
    int wh = blockIdx.x;
    int win = wh / HEADS, h = wh % HEADS;
    __shared__ float q[NN][HD + 1];
    __shared__ float k[NN][HD + 1];
    __shared__ float v[NN][HD + 1];
    __shared__ float s[NN][NN];
    int t = threadIdx.x;
    const float scale = 0.17677669529663687f;  // 1/sqrt(32)
    for (int idx = t; idx < NN * HD; idx += 128) {
        int r = idx >> 5, d = idx & 31;
        size_t base = ((size_t)win * NN + r) * (3 * CC) + h * HD + d;
        q[r][d] = g_qkv[base] * scale;
        k[r][d] = g_qkv[base + CC];
        v[r][d] = g_qkv[base + 2 * CC];
    }
    __syncthreads();
    for (int p = t; p < NN * NN; p += 128) {
        int i = p / NN, j = p % NN;
        float acc = 0.f;
        #pragma unroll
        for (int d = 0; d < HD; d++) acc += q[i][d] * k[j][d];
        s[i][j] = acc + g_bias[h * NN * NN + p];
    }
    __syncthreads();
    if (t < NN) {
        float mx = -1e30f;
        #pragma unroll
        for (int j = 0; j < NN; j++) mx = fmaxf(mx, s[t][j]);
        float sum = 0.f;
        #pragma unroll
        for (int j = 0; j < NN; j++) { float e = __expf(s[t][j] - mx); s[t][j] = e; sum += e; }
        float inv = 1.0f / sum;
        #pragma unroll
        for (int j = 0; j < NN; j++) s[t][j] *= inv;
    }
    __syncthreads();
    for (int p = t; p < NN * HD; p += 128) {
        int i = p >> 5, d = p & 31;
        float acc = 0.f;
        #pragma unroll
        for (int j = 0; j < NN; j++) acc += s[i][j] * v[j][d];
        g_attn[((size_t)win * NN + i) * CC + h * HD + d] = acc;
    }
}

// ----------------------------------------------------------------
extern "C" void kernel_launch(void* const* d_in, const int* in_sizes, int n_in,
                              void* d_out, int out_size) {
    const float* x       = (const float*)d_in[0];
    const float* n1g     = (const float*)d_in[1];
    const float* n1b     = (const float*)d_in[2];
    const float* qkv_w   = (const float*)d_in[3];
    const float* qkv_b   = (const float*)d_in[4];
    const float* proj_w  = (const float*)d_in[5];
    const float* proj_b  = (const float*)d_in[6];
    const float* table   = (const float*)d_in[7];
    const float* n2g     = (const float*)d_in[8];
    const float* n2b     = (const float*)d_in[9];
    const float* fc1_w   = (const float*)d_in[10];
    const float* fc1_b   = (const float*)d_in[11];
    const float* fc2_w   = (const float*)d_in[12];
    const float* fc2_b   = (const float*)d_in[13];
    const int*   relidx  = (const int*)d_in[14];
    float*       out     = (float*)d_out;

    float *p_win, *p_qkv, *p_attn, *p_res1, *p_hid;
    cudaGetSymbolAddress((void**)&p_win,  g_win);
    cudaGetSymbolAddress((void**)&p_qkv,  g_qkv);
    cudaGetSymbolAddress((void**)&p_attn, g_attn);
    cudaGetSymbolAddress((void**)&p_res1, g_res1);
    cudaGetSymbolAddress((void**)&p_hid,  g_hid);

    // 1) rel-pos bias gather
    bias_pre_kernel<<<(NN * NN + 127) / 128, 128>>>(table, relidx);
    // 2) LN1 + shift + window partition
    ln_shift_win_kernel<<<NTOK, 192>>>(x, n1g, n1b);
    // 3) QKV GEMM: [100352,192] x [576,192]^T
    gemm_nt<0><<<dim3(3 * CC / BN, NTOK / BM), 256>>>(p_win, qkv_w, qkv_b, nullptr, p_qkv,
                                                      NTOK, 3 * CC, CC);
    // 4) windowed attention
    attn_kernel<<<NWIN * HEADS, 128>>>();
    // 5) proj GEMM (output into g_win, window layout)
    gemm_nt<0><<<dim3(CC / BN, NTOK / BM), 256>>>(p_attn, proj_w, proj_b, nullptr, p_win,
                                                  NTOK, CC, CC);
    // 6) window reverse + unshift + residual + LN2 (ln2 out reuses g_attn)
    resid_ln2_kernel<<<NTOK, 192>>>(x, n2g, n2b);
    // 7) fc1 + exact GELU
    gemm_nt<1><<<dim3(HID / BN, NTOK / BM), 256>>>(p_attn, fc1_w, fc1_b, nullptr, p_hid,
                                                   NTOK, HID, CC);
    // 8) fc2 + residual -> d_out
    gemm_nt<2><<<dim3(CC / BN, NTOK / BM), 256>>>(p_hid, fc2_w, fc2_b, p_res1, out,
                                                  NTOK, CC, HID);
}

// round 10
// speedup vs baseline: 2.3184x; 2.3184x over previous
#include <cuda_runtime.h>
#include <cuda_bf16.h>
#include <math.h>

#define BB   32
#define HH   56
#define WWID 56
#define CC   192
#define HEADS 6
#define HD   32
#define WS   7
#define SHIFT 3
#define HID  768
#define NTOK (BB*HH*WWID)          // 100352
#define NWIN (BB*8*8)              // 2048
#define NN   (WS*WS)               // 49

// ---------------- scratch (device globals; no allocations allowed) ----------------
__device__ float g_qkv [(size_t)NTOK * 3 * CC];                     // qkv fp32
__device__ float g_win [(size_t)NTOK * CC];                         // proj out fp32 (window layout)
__device__ float g_res1[(size_t)NTOK * CC];                         // x + attn branch fp32
__device__ __align__(16) __nv_bfloat16 g_Ahi[(size_t)NTOK * CC];    // A hi (ln1out/attnout/ln2out)
__device__ __align__(16) __nv_bfloat16 g_Alo[(size_t)NTOK * CC];
__device__ __align__(16) __nv_bfloat16 g_Hhi[(size_t)NTOK * HID];   // fc1 out (gelu) hi
__device__ __align__(16) __nv_bfloat16 g_Hlo[(size_t)NTOK * HID];
#define W_QKV  0
#define W_PROJ 110592
#define W_FC1  147456
#define W_FC2  294912
#define W_TOT  442368
__device__ __align__(16) __nv_bfloat16 g_Whi[W_TOT];
__device__ __align__(16) __nv_bfloat16 g_Wlo[W_TOT];
__device__ float g_bias[HEADS * NN * NN];

// ---------------- helpers ----------------
__device__ __forceinline__ unsigned smem_u32(const void* p) {
    unsigned a;
    asm("{ .reg .u64 t; cvta.to.shared.u64 t, %1; cvt.u32.u64 %0, t; }" : "=r"(a) : "l"(p));
    return a;
}
__device__ __forceinline__ void cp16(unsigned dst, const void* src) {
    asm volatile("cp.async.cg.shared.global [%0], [%1], 16;" :: "r"(dst), "l"(src));
}
#define CP_COMMIT() asm volatile("cp.async.commit_group;")
#define CP_WAIT(n)  asm volatile("cp.async.wait_group %0;" :: "n"(n) : "memory")

__device__ __forceinline__ void mma16816(float* d, const unsigned* a, const unsigned* b) {
    asm volatile("mma.sync.aligned.m16n8k16.row.col.f32.bf16.bf16.f32 "
        "{%0,%1,%2,%3}, {%4,%5,%6,%7}, {%8,%9}, {%0,%1,%2,%3};"
        : "+f"(d[0]), "+f"(d[1]), "+f"(d[2]), "+f"(d[3])
        : "r"(a[0]), "r"(a[1]), "r"(a[2]), "r"(a[3]), "r"(b[0]), "r"(b[1]));
}

__device__ __forceinline__ void splitf(float v, __nv_bfloat16& h, __nv_bfloat16& l) {
    h = __float2bfloat16(v);
    l = __float2bfloat16(v - __bfloat162float(h));
}

// ---------------- small kernels ----------------
__global__ void bias_pre_kernel(const float* __restrict__ table, const int* __restrict__ relidx) {
    int p = blockIdx.x * blockDim.x + threadIdx.x;
    if (p < NN * NN) {
        int idx = relidx[p];
        #pragma unroll
        for (int h = 0; h < HEADS; h++)
            g_bias[h * NN * NN + p] = table[idx * HEADS + h];
    }
}

__global__ void split_weights(const float* __restrict__ qkv_w, const float* __restrict__ proj_w,
                              const float* __restrict__ fc1_w, const float* __restrict__ fc2_w) {
    int i = blockIdx.x * 256 + threadIdx.x;
    if (i >= W_TOT) return;
    float v;
    if      (i < W_PROJ) v = qkv_w [i];
    else if (i < W_FC1)  v = proj_w[i - W_PROJ];
    else if (i < W_FC2)  v = fc1_w [i - W_FC1];
    else                 v = fc2_w [i - W_FC2];
    __nv_bfloat16 h, l; splitf(v, h, l);
    g_Whi[i] = h; g_Wlo[i] = l;
}

// LN1 + shift + window partition -> bf16 hi/lo
__global__ void __launch_bounds__(192) ln_shift_win_kernel(
    const float* __restrict__ x, const float* __restrict__ g, const float* __restrict__ b) {
    int o = blockIdx.x;
    int win = o / NN, pos = o % NN;
    int bb = win >> 6, wi = (win >> 3) & 7, wj = win & 7;
    int i = pos / WS, j = pos % WS;
    int hs  = (wi * WS + i + SHIFT) % HH;
    int ws2 = (wj * WS + j + SHIFT) % WWID;
    const float* row = x + ((size_t)(bb * HH + hs) * WWID + ws2) * CC;
    int c = threadIdx.x;
    float v = row[c];
    float s = v, s2 = v * v;
    #pragma unroll
    for (int off = 16; off; off >>= 1) {
        s  += __shfl_down_sync(0xffffffffu, s,  off);
        s2 += __shfl_down_sync(0xffffffffu, s2, off);
    }
    __shared__ float sh[12];
    if ((threadIdx.x & 31) == 0) { sh[threadIdx.x >> 5] = s; sh[6 + (threadIdx.x >> 5)] = s2; }
    __syncthreads();
    float ts = 0.f, ts2 = 0.f;
    #pragma unroll
    for (int w = 0; w < 6; w++) { ts += sh[w]; ts2 += sh[6 + w]; }
    float mu = ts * (1.0f / CC);
    float var = ts2 * (1.0f / CC) - mu * mu;
    float rs = rsqrtf(var + 1e-5f);
    float oo = (v - mu) * rs * g[c] + b[c];
    __nv_bfloat16 h, l; splitf(oo, h, l);
    size_t idx = (size_t)o * CC + c;
    g_Ahi[idx] = h; g_Alo[idx] = l;
}

// window reverse + unshift + residual + LN2 -> g_res1 fp32, ln2 out bf16 hi/lo
__global__ void __launch_bounds__(192) resid_ln2_kernel(
    const float* __restrict__ x, const float* __restrict__ g, const float* __restrict__ b) {
    int t = blockIdx.x;
    int bb = t / (HH * WWID); int rem = t % (HH * WWID);
    int h = rem / WWID, w = rem % WWID;
    int h2 = (h + HH - SHIFT) % HH, w2 = (w + WWID - SHIFT) % WWID;
    int o = ((bb * 64 + (h2 / WS) * 8 + (w2 / WS)) * NN + (h2 % WS) * WS + (w2 % WS));
    int c = threadIdx.x;
    float v = x[(size_t)t * CC + c] + g_win[(size_t)o * CC + c];
    g_res1[(size_t)t * CC + c] = v;
    float s = v, s2 = v * v;
    #pragma unroll
    for (int off = 16; off; off >>= 1) {
        s  += __shfl_down_sync(0xffffffffu, s,  off);
        s2 += __shfl_down_sync(0xffffffffu, s2, off);
    }
    __shared__ float sh[12];
    if ((threadIdx.x & 31) == 0) { sh[threadIdx.x >> 5] = s; sh[6 + (threadIdx.x >> 5)] = s2; }
    __syncthreads();
    float ts = 0.f, ts2 = 0.f;
    #pragma unroll
    for (int ww = 0; ww < 6; ww++) { ts += sh[ww]; ts2 += sh[6 + ww]; }
    float mu = ts * (1.0f / CC);
    float var = ts2 * (1.0f / CC) - mu * mu;
    float rs = rsqrtf(var + 1e-5f);
    float oo = (v - mu) * rs * g[c] + b[c];
    __nv_bfloat16 hh, ll; splitf(oo, hh, ll);
    size_t idx = (size_t)t * CC + c;
    g_Ahi[idx] = hh; g_Alo[idx] = ll;
}

// ---------------- mma.sync GEMM: D[m,n] = sum_k A[m,k]*Bw[n,k] + bias, bf16x2 split ----------------
// BM=128, BN=96, BK=32, 256 threads (8 warps as 4x2), warp tile 32x48.
#define BM 128
#define BN 96
#define BK 32
#define PADK 40                          // padded row stride (bf16 elems): 80B, 16B-aligned, conflict-free
#define ASZ (BM * PADK * 2)              // 10240 B per A matrix tile
#define BSZ (BN * PADK * 2)              // 7680 B per B matrix tile
#define STG (2 * ASZ + 2 * BSZ)          // 35840 B per stage (Ah, Al, Bh, Bl)
#define GSMEM (2 * STG)                  // 71680 B

// EPI: 0 = +bias -> fp32 ; 1 = gelu(+bias) -> bf16 hi/lo ; 2 = +bias+res -> fp32
template<int EPI>
__global__ void __launch_bounds__(256) mma_gemm(
    const __nv_bfloat16* __restrict__ Ahi, const __nv_bfloat16* __restrict__ Alo,
    const __nv_bfloat16* __restrict__ Bhi, const __nv_bfloat16* __restrict__ Blo,
    const float* __restrict__ bias, const float* __restrict__ res,
    float* __restrict__ outF, __nv_bfloat16* __restrict__ outHi, __nv_bfloat16* __restrict__ outLo,
    int N, int K)
{
    extern __shared__ __align__(16) char smem[];
    const unsigned sb = smem_u32(smem);
    const int t = threadIdx.x, wid = t >> 5, lane = t & 31;
    const int warpM = wid >> 1, warpN = wid & 1;
    const int g = lane >> 2, t4 = lane & 3;
    const int m0 = blockIdx.y * BM;
    const int n0 = blockIdx.x * BN;
    const int nchunks = K / BK;

    // ---- async tile loader for chunk c into stage s ----
    auto load_chunk = [&](int c, int s) {
        const int k0 = c * BK;
        const unsigned sa = sb + s * STG;
        #pragma unroll
        for (int u0 = 0; u0 < 1024; u0 += 256) {
            int u = u0 + t;
            int mat = u >> 9, r = (u >> 2) & 127, q = u & 3;
            const __nv_bfloat16* src = (mat ? Alo : Ahi) + (size_t)(m0 + r) * K + k0 + q * 8;
            cp16(sa + mat * ASZ + r * (PADK * 2) + q * 16, src);
        }
        const unsigned sbb = sa + 2 * ASZ;
        #pragma unroll
        for (int u0 = 0; u0 < 768; u0 += 256) {
            int u = u0 + t;
            int mat = (u >= 384) ? 1 : 0, uu = u - mat * 384;
            int r = uu >> 2, q = uu & 3;
            const __nv_bfloat16* src = (mat ? Blo : Bhi) + (size_t)(n0 + r) * K + k0 + q * 8;
            cp16(sbb + mat * BSZ + r * (PADK * 2) + q * 16, src);
        }
        CP_COMMIT();
    };

    float acc[2][6][4];
    #pragma unroll
    for (int i = 0; i < 2; i++)
        #pragma unroll
        for (int j = 0; j < 6; j++)
            #pragma unroll
            for (int q = 0; q < 4; q++) acc[i][j][q] = 0.f;

    load_chunk(0, 0);

    for (int c = 0; c < nchunks; c++) {
        if (c + 1 < nchunks) load_chunk(c + 1, (c + 1) & 1);
        if (c + 1 < nchunks) { CP_WAIT(1); } else { CP_WAIT(0); }
        __syncthreads();

        const char* st = smem + (c & 1) * STG;
        const char* pAh = st;
        const char* pAl = st + ASZ;
        const char* pBh = st + 2 * ASZ;
        const char* pBl = st + 2 * ASZ + BSZ;

        #pragma unroll
        for (int kk = 0; kk < BK; kk += 16) {
            unsigned ah[2][4], al[2][4], bh[6][2], bl[6][2];
            const int ck = kk + t4 * 2;
            #pragma unroll
            for (int mt = 0; mt < 2; mt++) {
                int r0 = warpM * 32 + mt * 16 + g;
                ah[mt][0] = *(const unsigned*)(pAh + (r0 * PADK + ck) * 2);
                ah[mt][1] = *(const unsigned*)(pAh + ((r0 + 8) * PADK + ck) * 2);
                ah[mt][2] = *(const unsigned*)(pAh + (r0 * PADK + ck + 8) * 2);
                ah[mt][3] = *(const unsigned*)(pAh + ((r0 + 8) * PADK + ck + 8) * 2);
                al[mt][0] = *(const unsigned*)(pAl + (r0 * PADK + ck) * 2);
                al[mt][1] = *(const unsigned*)(pAl + ((r0 + 8) * PADK + ck) * 2);
                al[mt][2] = *(const unsigned*)(pAl + (r0 * PADK + ck + 8) * 2);
                al[mt][3] = *(const unsigned*)(pAl + ((r0 + 8) * PADK + ck + 8) * 2);
            }
            #pragma unroll
            for (int nt = 0; nt < 6; nt++) {
                int n = warpN * 48 + nt * 8 + g;
                bh[nt][0] = *(const unsigned*)(pBh + (n * PADK + ck) * 2);
                bh[nt][1] = *(const unsigned*)(pBh + (n * PADK + ck + 8) * 2);
                bl[nt][0] = *(const unsigned*)(pBl + (n * PADK + ck) * 2);
                bl[nt][1] = *(const unsigned*)(pBl + (n * PADK + ck + 8) * 2);
            }
            #pragma unroll
            for (int mt = 0; mt < 2; mt++)
                #pragma unroll
                for (int nt = 0; nt < 6; nt++) {
                    mma16816(acc[mt][nt], ah[mt], bh[nt]);
                    mma16816(acc[mt][nt], ah[mt], bl[nt]);
                    mma16816(acc[mt][nt], al[mt], bh[nt]);
                }
        }
        __syncthreads();
    }

    // ---- epilogue ----
    #pragma unroll
    for (int mt = 0; mt < 2; mt++) {
        int m = m0 + warpM * 32 + mt * 16 + g;
        #pragma unroll
        for (int nt = 0; nt < 6; nt++) {
            int n = n0 + warpN * 48 + nt * 8 + t4 * 2;
            float b0 = bias[n], b1 = bias[n + 1];
            #pragma unroll
            for (int half = 0; half < 2; half++) {
                int mr = m + half * 8;
                float v0 = acc[mt][nt][2 * half]     + b0;
                float v1 = acc[mt][nt][2 * half + 1] + b1;
                size_t base = (size_t)mr * N + n;
                if (EPI == 1) {
                    v0 = 0.5f * v0 * (1.0f + erff(v0 * 0.7071067811865476f));
                    v1 = 0.5f * v1 * (1.0f + erff(v1 * 0.7071067811865476f));
                    __nv_bfloat16 h0, l0, h1, l1;
                    splitf(v0, h0, l0); splitf(v1, h1, l1);
                    *(unsigned*)(outHi + base) =
                        (unsigned)__bfloat16_as_ushort(h0) | ((unsigned)__bfloat16_as_ushort(h1) << 16);
                    *(unsigned*)(outLo + base) =
                        (unsigned)__bfloat16_as_ushort(l0) | ((unsigned)__bfloat16_as_ushort(l1) << 16);
                } else {
                    if (EPI == 2) {
                        float2 rv = *(const float2*)(res + base);
                        v0 += rv.x; v1 += rv.y;
                    }
                    *(float2*)(outF + base) = make_float2(v0, v1);
                }
            }
        }
    }
}

// ---------------- per-(window, head) attention (fp32 in, bf16-split out) ----------------
__global__ void __launch_bounds__(128) attn_kernel() {
    int wh = blockIdx.x;
    int win = wh / HEADS, h = wh % HEADS;
    __shared__ float q[NN][HD + 1];
    __shared__ float k[NN][HD + 1];
    __shared__ float v[NN][HD + 1];
    __shared__ float s[NN][NN];
    int t = threadIdx.x;
    const float scale = 0.17677669529663687f;
    for (int idx = t; idx < NN * HD; idx += 128) {
        int r = idx >> 5, d = idx & 31;
        size_t base = ((size_t)win * NN + r) * (3 * CC) + h * HD + d;
        q[r][d] = g_qkv[base] * scale;
        k[r][d] = g_qkv[base + CC];
        v[r][d] = g_qkv[base + 2 * CC];
    }
    __syncthreads();
    for (int p = t; p < NN * NN; p += 128) {
        int i = p / NN, j = p % NN;
        float acc = 0.f;
        #pragma unroll
        for (int d = 0; d < HD; d++) acc += q[i][d] * k[j][d];
        s[i][j] = acc + g_bias[h * NN * NN + p];
    }
    __syncthreads();
    if (t < NN) {
        float mx = -1e30f;
        #pragma unroll
        for (int j = 0; j < NN; j++) mx = fmaxf(mx, s[t][j]);
        float sum = 0.f;
        #pragma unroll
        for (int j = 0; j < NN; j++) { float e = __expf(s[t][j] - mx); s[t][j] = e; sum += e; }
        float inv = 1.0f / sum;
        #pragma unroll
        for (int j = 0; j < NN; j++) s[t][j] *= inv;
    }
    __syncthreads();
    for (int p = t; p < NN * HD; p += 128) {
        int i = p >> 5, d = p & 31;
        float acc = 0.f;
        #pragma unroll
        for (int j = 0; j < NN; j++) acc += s[i][j] * v[j][d];
        size_t idx = ((size_t)win * NN + i) * CC + h * HD + d;
        __nv_bfloat16 hh, ll; splitf(acc, hh, ll);
        g_Ahi[idx] = hh; g_Alo[idx] = ll;
    }
}

// ----------------------------------------------------------------
extern "C" void kernel_launch(void* const* d_in, const int* in_sizes, int n_in,
                              void* d_out, int out_size) {
    const float* x      = (const float*)d_in[0];
    const float* n1g    = (const float*)d_in[1];
    const float* n1b    = (const float*)d_in[2];
    const float* qkv_w  = (const float*)d_in[3];
    const float* qkv_b  = (const float*)d_in[4];
    const float* proj_w = (const float*)d_in[5];
    const float* proj_b = (const float*)d_in[6];
    const float* table  = (const float*)d_in[7];
    const float* n2g    = (const float*)d_in[8];
    const float* n2b    = (const float*)d_in[9];
    const float* fc1_w  = (const float*)d_in[10];
    const float* fc1_b  = (const float*)d_in[11];
    const float* fc2_w  = (const float*)d_in[12];
    const float* fc2_b  = (const float*)d_in[13];
    const int*   relidx = (const int*)d_in[14];
    float*       out    = (float*)d_out;

    float *p_qkv, *p_win, *p_res1;
    __nv_bfloat16 *p_Ahi, *p_Alo, *p_Hhi, *p_Hlo, *p_Whi, *p_Wlo;
    cudaGetSymbolAddress((void**)&p_qkv,  g_qkv);
    cudaGetSymbolAddress((void**)&p_win,  g_win);
    cudaGetSymbolAddress((void**)&p_res1, g_res1);
    cudaGetSymbolAddress((void**)&p_Ahi,  g_Ahi);
    cudaGetSymbolAddress((void**)&p_Alo,  g_Alo);
    cudaGetSymbolAddress((void**)&p_Hhi,  g_Hhi);
    cudaGetSymbolAddress((void**)&p_Hlo,  g_Hlo);
    cudaGetSymbolAddress((void**)&p_Whi,  g_Whi);
    cudaGetSymbolAddress((void**)&p_Wlo,  g_Wlo);

    cudaFuncSetAttribute((const void*)mma_gemm<0>, cudaFuncAttributeMaxDynamicSharedMemorySize, GSMEM);
    cudaFuncSetAttribute((const void*)mma_gemm<1>, cudaFuncAttributeMaxDynamicSharedMemorySize, GSMEM);
    cudaFuncSetAttribute((const void*)mma_gemm<2>, cudaFuncAttributeMaxDynamicSharedMemorySize, GSMEM);

    // 1) rel-pos bias gather + weight split
    bias_pre_kernel<<<(NN * NN + 127) / 128, 128>>>(table, relidx);
    split_weights<<<(W_TOT + 255) / 256, 256>>>(qkv_w, proj_w, fc1_w, fc2_w);
    // 2) LN1 + shift + window partition -> A hi/lo
    ln_shift_win_kernel<<<NTOK, 192>>>(x, n1g, n1b);
    // 3) QKV GEMM: [100352,192] x [576,192]^T -> g_qkv fp32
    mma_gemm<0><<<dim3(3 * CC / BN, NTOK / BM), 256, GSMEM>>>(
        p_Ahi, p_Alo, p_Whi + W_QKV, p_Wlo + W_QKV, qkv_b, nullptr,
        p_qkv, nullptr, nullptr, 3 * CC, CC);
    // 4) windowed attention -> A hi/lo (attn out)
    attn_kernel<<<NWIN * HEADS, 128>>>();
    // 5) proj GEMM -> g_win fp32 (window layout)
    mma_gemm<0><<<dim3(CC / BN, NTOK / BM), 256, GSMEM>>>(
        p_Ahi, p_Alo, p_Whi + W_PROJ, p_Wlo + W_PROJ, proj_b, nullptr,
        p_win, nullptr, nullptr, CC, CC);
    // 6) window reverse + unshift + residual + LN2 -> g_res1 fp32, A hi/lo (ln2 out)
    resid_ln2_kernel<<<NTOK, 192>>>(x, n2g, n2b);
    // 7) fc1 + exact GELU -> H hi/lo
    mma_gemm<1><<<dim3(HID / BN, NTOK / BM), 256, GSMEM>>>(
        p_Ahi, p_Alo, p_Whi + W_FC1, p_Wlo + W_FC1, fc1_b, nullptr,
        nullptr, p_Hhi, p_Hlo, HID, CC);
    // 8) fc2 + residual -> d_out fp32
    mma_gemm<2><<<dim3(CC / BN, NTOK / BM), 256, GSMEM>>>(
        p_Hhi, p_Hlo, p_Whi + W_FC2, p_Wlo + W_FC2, fc2_b, p_res1,
        out, nullptr, nullptr, CC, HID);
}

// round 11
// speedup vs baseline: 3.0252x; 1.3048x over previous
#include <cuda_runtime.h>
#include <cuda_bf16.h>
#include <math.h>

#define BB   32
#define HH   56
#define WWID 56
#define CC   192
#define HEADS 6
#define HD   32
#define WS   7
#define SHIFT 3
#define HID  768
#define NTOK (BB*HH*WWID)          // 100352
#define NWIN (BB*8*8)              // 2048
#define NN   (WS*WS)               // 49

// ---------------- scratch (device globals; no allocations allowed) ----------------
__device__ float g_win [(size_t)NTOK * CC];                         // proj out fp32 (window layout)
__device__ float g_res1[(size_t)NTOK * CC];                         // x + attn branch fp32
__device__ __align__(16) __nv_bfloat16 g_Ahi[(size_t)NTOK * CC];    // A hi (ln1out/attnout/ln2out)
__device__ __align__(16) __nv_bfloat16 g_Alo[(size_t)NTOK * CC];
__device__ __align__(16) __nv_bfloat16 g_Hhi[(size_t)NTOK * HID];   // qkv hi (576) then fc1 out hi (768)
__device__ __align__(16) __nv_bfloat16 g_Hlo[(size_t)NTOK * HID];
#define W_QKV  0
#define W_PROJ 110592
#define W_FC1  147456
#define W_FC2  294912
#define W_TOT  442368
__device__ __align__(16) __nv_bfloat16 g_Whi[W_TOT];
__device__ __align__(16) __nv_bfloat16 g_Wlo[W_TOT];
__device__ float g_bias[HEADS * NN * NN];

// ---------------- helpers ----------------
__device__ __forceinline__ unsigned smem_u32(const void* p) {
    unsigned a;
    asm("{ .reg .u64 t; cvta.to.shared.u64 t, %1; cvt.u32.u64 %0, t; }" : "=r"(a) : "l"(p));
    return a;
}
__device__ __forceinline__ void cp16(unsigned dst, const void* src) {
    asm volatile("cp.async.cg.shared.global [%0], [%1], 16;" :: "r"(dst), "l"(src));
}
#define CP_COMMIT() asm volatile("cp.async.commit_group;")
#define CP_WAIT(n)  asm volatile("cp.async.wait_group %0;" :: "n"(n) : "memory")

__device__ __forceinline__ void mma16816(float* d, const unsigned* a, const unsigned* b) {
    asm volatile("mma.sync.aligned.m16n8k16.row.col.f32.bf16.bf16.f32 "
        "{%0,%1,%2,%3}, {%4,%5,%6,%7}, {%8,%9}, {%0,%1,%2,%3};"
        : "+f"(d[0]), "+f"(d[1]), "+f"(d[2]), "+f"(d[3])
        : "r"(a[0]), "r"(a[1]), "r"(a[2]), "r"(a[3]), "r"(b[0]), "r"(b[1]));
}
__device__ __forceinline__ void ldsm4(unsigned* r, unsigned a) {
    asm volatile("ldmatrix.sync.aligned.m8n8.x4.shared.b16 {%0,%1,%2,%3}, [%4];"
        : "=r"(r[0]), "=r"(r[1]), "=r"(r[2]), "=r"(r[3]) : "r"(a));
}
__device__ __forceinline__ void ldsm4t(unsigned* r, unsigned a) {
    asm volatile("ldmatrix.sync.aligned.m8n8.x4.trans.shared.b16 {%0,%1,%2,%3}, [%4];"
        : "=r"(r[0]), "=r"(r[1]), "=r"(r[2]), "=r"(r[3]) : "r"(a));
}

__device__ __forceinline__ void splitf(float v, __nv_bfloat16& h, __nv_bfloat16& l) {
    h = __float2bfloat16(v);
    l = __float2bfloat16(v - __bfloat162float(h));
}
// pack (x,y) into bf16x2 hi word + bf16x2 lo (residual) word
__device__ __forceinline__ void packsplit(float x, float y, unsigned& hi, unsigned& lo) {
    __nv_bfloat16 hx = __float2bfloat16(x), hy = __float2bfloat16(y);
    float rx = x - __bfloat162float(hx), ry = y - __bfloat162float(hy);
    hi = (unsigned)__bfloat16_as_ushort(hx) | ((unsigned)__bfloat16_as_ushort(hy) << 16);
    lo = (unsigned)__bfloat16_as_ushort(__float2bfloat16(rx))
       | ((unsigned)__bfloat16_as_ushort(__float2bfloat16(ry)) << 16);
}

// ---------------- small kernels ----------------
__global__ void bias_pre_kernel(const float* __restrict__ table, const int* __restrict__ relidx) {
    int p = blockIdx.x * blockDim.x + threadIdx.x;
    if (p < NN * NN) {
        int idx = relidx[p];
        #pragma unroll
        for (int h = 0; h < HEADS; h++)
            g_bias[h * NN * NN + p] = table[idx * HEADS + h];
    }
}

__global__ void split_weights(const float* __restrict__ qkv_w, const float* __restrict__ proj_w,
                              const float* __restrict__ fc1_w, const float* __restrict__ fc2_w) {
    int i = blockIdx.x * 256 + threadIdx.x;
    if (i >= W_TOT) return;
    float v;
    if      (i < W_PROJ) v = qkv_w [i];
    else if (i < W_FC1)  v = proj_w[i - W_PROJ];
    else if (i < W_FC2)  v = fc1_w [i - W_FC1];
    else                 v = fc2_w [i - W_FC2];
    __nv_bfloat16 h, l; splitf(v, h, l);
    g_Whi[i] = h; g_Wlo[i] = l;
}

// LN1 + shift + window partition -> bf16 hi/lo
__global__ void __launch_bounds__(192) ln_shift_win_kernel(
    const float* __restrict__ x, const float* __restrict__ g, const float* __restrict__ b) {
    int o = blockIdx.x;
    int win = o / NN, pos = o % NN;
    int bb = win >> 6, wi = (win >> 3) & 7, wj = win & 7;
    int i = pos / WS, j = pos % WS;
    int hs  = (wi * WS + i + SHIFT) % HH;
    int ws2 = (wj * WS + j + SHIFT) % WWID;
    const float* row = x + ((size_t)(bb * HH + hs) * WWID + ws2) * CC;
    int c = threadIdx.x;
    float v = row[c];
    float s = v, s2 = v * v;
    #pragma unroll
    for (int off = 16; off; off >>= 1) {
        s  += __shfl_down_sync(0xffffffffu, s,  off);
        s2 += __shfl_down_sync(0xffffffffu, s2, off);
    }
    __shared__ float sh[12];
    if ((threadIdx.x & 31) == 0) { sh[threadIdx.x >> 5] = s; sh[6 + (threadIdx.x >> 5)] = s2; }
    __syncthreads();
    float ts = 0.f, ts2 = 0.f;
    #pragma unroll
    for (int w = 0; w < 6; w++) { ts += sh[w]; ts2 += sh[6 + w]; }
    float mu = ts * (1.0f / CC);
    float var = ts2 * (1.0f / CC) - mu * mu;
    float rs = rsqrtf(var + 1e-5f);
    float oo = (v - mu) * rs * g[c] + b[c];
    __nv_bfloat16 h, l; splitf(oo, h, l);
    size_t idx = (size_t)o * CC + c;
    g_Ahi[idx] = h; g_Alo[idx] = l;
}

// window reverse + unshift + residual + LN2 -> g_res1 fp32, ln2 out bf16 hi/lo
__global__ void __launch_bounds__(192) resid_ln2_kernel(
    const float* __restrict__ x, const float* __restrict__ g, const float* __restrict__ b) {
    int t = blockIdx.x;
    int bb = t / (HH * WWID); int rem = t % (HH * WWID);
    int h = rem / WWID, w = rem % WWID;
    int h2 = (h + HH - SHIFT) % HH, w2 = (w + WWID - SHIFT) % WWID;
    int o = ((bb * 64 + (h2 / WS) * 8 + (w2 / WS)) * NN + (h2 % WS) * WS + (w2 % WS));
    int c = threadIdx.x;
    float v = x[(size_t)t * CC + c] + g_win[(size_t)o * CC + c];
    g_res1[(size_t)t * CC + c] = v;
    float s = v, s2 = v * v;
    #pragma unroll
    for (int off = 16; off; off >>= 1) {
        s  += __shfl_down_sync(0xffffffffu, s,  off);
        s2 += __shfl_down_sync(0xffffffffu, s2, off);
    }
    __shared__ float sh[12];
    if ((threadIdx.x & 31) == 0) { sh[threadIdx.x >> 5] = s; sh[6 + (threadIdx.x >> 5)] = s2; }
    __syncthreads();
    float ts = 0.f, ts2 = 0.f;
    #pragma unroll
    for (int ww = 0; ww < 6; ww++) { ts += sh[ww]; ts2 += sh[6 + ww]; }
    float mu = ts * (1.0f / CC);
    float var = ts2 * (1.0f / CC) - mu * mu;
    float rs = rsqrtf(var + 1e-5f);
    float oo = (v - mu) * rs * g[c] + b[c];
    __nv_bfloat16 hh, ll; splitf(oo, hh, ll);
    size_t idx = (size_t)t * CC + c;
    g_Ahi[idx] = hh; g_Alo[idx] = ll;
}

// ---------------- mma.sync GEMM: D[m,n] = sum_k A[m,k]*Bw[n,k] + bias, bf16x2 split ----------------
// BM=128, BN=96, BK=32, 256 threads (8 warps as 4x2), warp tile 32x48. ldmatrix fragment loads.
#define BM 128
#define BN 96
#define BK 32
#define PADK 40                          // padded row stride (bf16): 80B, 16B-aligned, LDSM conflict-free
#define ASZ (BM * PADK * 2)              // 10240 B per A matrix tile
#define BSZ (BN * PADK * 2)              // 7680 B per B matrix tile
#define STG (2 * ASZ + 2 * BSZ)          // 35840 B per stage (Ah, Al, Bh, Bl)
#define GSMEM (2 * STG)                  // 71680 B

// EPI: 0 = +bias -> fp32 ; 1 = gelu(+bias) -> bf16 hi/lo ; 2 = +bias+res -> fp32 ; 3 = +bias -> bf16 hi/lo
template<int EPI>
__global__ void __launch_bounds__(256) mma_gemm(
    const __nv_bfloat16* __restrict__ Ahi, const __nv_bfloat16* __restrict__ Alo,
    const __nv_bfloat16* __restrict__ Bhi, const __nv_bfloat16* __restrict__ Blo,
    const float* __restrict__ bias, const float* __restrict__ res,
    float* __restrict__ outF, __nv_bfloat16* __restrict__ outHi, __nv_bfloat16* __restrict__ outLo,
    int N, int K)
{
    extern __shared__ __align__(16) char smem[];
    const unsigned sb = smem_u32(smem);
    const int t = threadIdx.x, wid = t >> 5, lane = t & 31;
    const int warpM = wid >> 1, warpN = wid & 1;
    const int g = lane >> 2, t4 = lane & 3;
    const int m0 = blockIdx.y * BM;
    const int n0 = blockIdx.x * BN;
    const int nchunks = K / BK;

    auto load_chunk = [&](int c, int s) {
        const int k0 = c * BK;
        const unsigned sa = sb + s * STG;
        #pragma unroll
        for (int u0 = 0; u0 < 1024; u0 += 256) {
            int u = u0 + t;
            int mat = u >> 9, r = (u >> 2) & 127, q = u & 3;
            const __nv_bfloat16* src = (mat ? Alo : Ahi) + (size_t)(m0 + r) * K + k0 + q * 8;
            cp16(sa + mat * ASZ + r * (PADK * 2) + q * 16, src);
        }
        const unsigned sbb = sa + 2 * ASZ;
        #pragma unroll
        for (int u0 = 0; u0 < 768; u0 += 256) {
            int u = u0 + t;
            int mat = (u >= 384) ? 1 : 0, uu = u - mat * 384;
            int r = uu >> 2, q = uu & 3;
            const __nv_bfloat16* src = (mat ? Blo : Bhi) + (size_t)(n0 + r) * K + k0 + q * 8;
            cp16(sbb + mat * BSZ + r * (PADK * 2) + q * 16, src);
        }
        CP_COMMIT();
    };

    float acc[2][6][4];
    #pragma unroll
    for (int i = 0; i < 2; i++)
        #pragma unroll
        for (int j = 0; j < 6; j++)
            #pragma unroll
            for (int q = 0; q < 4; q++) acc[i][j][q] = 0.f;

    // lane-invariant pieces of ldmatrix addresses
    const int arow = (lane & 15);               // A: row within 16
    const int acol = ((lane >> 4) << 3);        // A: k half
    const int brow = ((lane >> 4) << 3) + (lane & 7);   // B: row within 16 (2 n-tiles)
    const int bcol = ((lane >> 3) & 1) * 8;             // B: k half

    load_chunk(0, 0);

    for (int c = 0; c < nchunks; c++) {
        if (c + 1 < nchunks) load_chunk(c + 1, (c + 1) & 1);
        if (c + 1 < nchunks) { CP_WAIT(1); } else { CP_WAIT(0); }
        __syncthreads();

        const unsigned su = sb + (c & 1) * STG;

        #pragma unroll
        for (int kk = 0; kk < BK; kk += 16) {
            unsigned ah[2][4], al[2][4], bh[3][4], bl[3][4];
            #pragma unroll
            for (int mt = 0; mt < 2; mt++) {
                unsigned aaddr = su + ((warpM * 32 + mt * 16 + arow) * PADK + kk + acol) * 2;
                ldsm4(ah[mt], aaddr);
                ldsm4(al[mt], aaddr + ASZ);
            }
            #pragma unroll
            for (int p2 = 0; p2 < 3; p2++) {
                unsigned baddr = su + 2 * ASZ
                    + ((warpN * 48 + p2 * 16 + brow) * PADK + kk + bcol) * 2;
                ldsm4(bh[p2], baddr);
                ldsm4(bl[p2], baddr + BSZ);
            }
            #pragma unroll
            for (int mt = 0; mt < 2; mt++)
                #pragma unroll
                for (int nt = 0; nt < 6; nt++) {
                    const unsigned* pbh = bh[nt >> 1] + (nt & 1) * 2;
                    const unsigned* pbl = bl[nt >> 1] + (nt & 1) * 2;
                    mma16816(acc[mt][nt], ah[mt], pbh);
                    mma16816(acc[mt][nt], ah[mt], pbl);
                    mma16816(acc[mt][nt], al[mt], pbh);
                }
        }
        __syncthreads();
    }

    // ---- epilogue ----
    #pragma unroll
    for (int mt = 0; mt < 2; mt++) {
        int m = m0 + warpM * 32 + mt * 16 + g;
        #pragma unroll
        for (int nt = 0; nt < 6; nt++) {
            int n = n0 + warpN * 48 + nt * 8 + t4 * 2;
            float b0 = bias[n], b1 = bias[n + 1];
            #pragma unroll
            for (int half = 0; half < 2; half++) {
                int mr = m + half * 8;
                float v0 = acc[mt][nt][2 * half]     + b0;
                float v1 = acc[mt][nt][2 * half + 1] + b1;
                size_t base = (size_t)mr * N + n;
                if (EPI == 1 || EPI == 3) {
                    if (EPI == 1) {
                        v0 = 0.5f * v0 * (1.0f + erff(v0 * 0.7071067811865476f));
                        v1 = 0.5f * v1 * (1.0f + erff(v1 * 0.7071067811865476f));
                    }
                    unsigned hw, lw;
                    packsplit(v0, v1, hw, lw);
                    *(unsigned*)(outHi + base) = hw;
                    *(unsigned*)(outLo + base) = lw;
                } else {
                    if (EPI == 2) {
                        float2 rv = *(const float2*)(res + base);
                        v0 += rv.x; v1 += rv.y;
                    }
                    *(float2*)(outF + base) = make_float2(v0, v1);
                }
            }
        }
    }
}

// ---------------- HMMA attention: one block per (window, head), 4 warps ----------------
// Q,K,V tiles (padded 49->64 rows) in smem as bf16 hi/lo; S=QK^T and O=PV via m16n8k16
// with 3-term bf16x2 compensation; fragment-resident masked softmax.
#define APAD 40   // row stride in bf16 (80 B)
__global__ void __launch_bounds__(128) attn_kernel() {
    const int wh = blockIdx.x;
    const int win = wh / HEADS, h = wh % HEADS;
    __shared__ __align__(16) __nv_bfloat16 sT[6][64 * APAD];  // Qh,Ql,Kh,Kl,Vh,Vl
    const int t = threadIdx.x, wid = t >> 5, lane = t & 31;
    const int g = lane >> 2, t4 = lane & 3;

    // zero-fill pad rows 49..63 (cols 0..31 only; ldmatrix never reads cols 32+)
    for (int u = t; u < 360; u += 128) {
        int tile = u / 60, rem = u % 60;
        int rr = 49 + (rem >> 2), q4 = rem & 3;
        *(uint4*)((char*)sT[tile] + rr * (APAD * 2) + q4 * 16) = make_uint4(0, 0, 0, 0);
    }
    // async loads: tiles 0/2/4 = hi (Q,K,V), 1/3/5 = lo
    for (int u = t; u < 1176; u += 128) {
        int tile = u / 196, rem = u % 196;
        int rr = rem >> 2, q4 = rem & 3;
        const __nv_bfloat16* src = ((tile & 1) ? g_Hlo : g_Hhi)
            + (size_t)(win * NN + rr) * 576 + (tile >> 1) * CC + h * HD + q4 * 8;
        cp16(smem_u32((char*)sT[tile] + rr * (APAD * 2) + q4 * 16), src);
    }
    CP_COMMIT(); CP_WAIT(0);
    __syncthreads();

    const unsigned sQh = smem_u32(sT[0]), sQl = smem_u32(sT[1]);
    const unsigned sKh = smem_u32(sT[2]), sKl = smem_u32(sT[3]);
    const unsigned sVh = smem_u32(sT[4]), sVl = smem_u32(sT[5]);

    // ---- S = Q @ K^T  (64x64, K=32) ----
    float sc[8][4];
    #pragma unroll
    for (int i = 0; i < 8; i++)
        #pragma unroll
        for (int e = 0; e < 4; e++) sc[i][e] = 0.f;

    const int arow = (lane & 15), acol = ((lane >> 4) << 3);
    const int brow = ((lane >> 4) << 3) + (lane & 7), bcol = ((lane >> 3) & 1) * 8;

    #pragma unroll
    for (int kk = 0; kk < 2; kk++) {
        unsigned ah[4], al[4];
        unsigned qaddr = ((wid * 16 + arow) * APAD + kk * 16 + acol) * 2;
        ldsm4(ah, sQh + qaddr);
        ldsm4(al, sQl + qaddr);
        #pragma unroll
        for (int p2 = 0; p2 < 4; p2++) {
            unsigned bh[4], bl[4];
            unsigned kaddr = ((p2 * 16 + brow) * APAD + kk * 16 + bcol) * 2;
            ldsm4(bh, sKh + kaddr);
            ldsm4(bl, sKl + kaddr);
            #pragma unroll
            for (int half = 0; half < 2; half++) {
                mma16816(sc[2 * p2 + half], ah, bh + half * 2);
                mma16816(sc[2 * p2 + half], ah, bl + half * 2);
                mma16816(sc[2 * p2 + half], al, bh + half * 2);
            }
        }
    }

    // ---- logits: scale + rel-pos bias + mask ----
    const int r0 = wid * 16 + g, r1 = r0 + 8;
    const float scale = 0.17677669529663687f;
    #pragma unroll
    for (int nt = 0; nt < 8; nt++) {
        #pragma unroll
        for (int e = 0; e < 4; e++) {
            int r = (e < 2) ? r0 : r1;
            int j = nt * 8 + t4 * 2 + (e & 1);
            float v = -1e30f;
            if (r < NN && j < NN)
                v = sc[nt][e] * scale + g_bias[h * NN * NN + r * NN + j];
            sc[nt][e] = v;
        }
    }
    // ---- softmax over fragments (rows r0, r1), quad-reduce across t4 lanes ----
    float mx0 = -1e30f, mx1 = -1e30f;
    #pragma unroll
    for (int nt = 0; nt < 8; nt++) {
        mx0 = fmaxf(mx0, fmaxf(sc[nt][0], sc[nt][1]));
        mx1 = fmaxf(mx1, fmaxf(sc[nt][2], sc[nt][3]));
    }
    #pragma unroll
    for (int off = 1; off < 4; off <<= 1) {
        mx0 = fmaxf(mx0, __shfl_xor_sync(0xffffffffu, mx0, off));
        mx1 = fmaxf(mx1, __shfl_xor_sync(0xffffffffu, mx1, off));
    }
    float sum0 = 0.f, sum1 = 0.f;
    #pragma unroll
    for (int nt = 0; nt < 8; nt++) {
        sc[nt][0] = __expf(sc[nt][0] - mx0); sum0 += sc[nt][0];
        sc[nt][1] = __expf(sc[nt][1] - mx0); sum0 += sc[nt][1];
        sc[nt][2] = __expf(sc[nt][2] - mx1); sum1 += sc[nt][2];
        sc[nt][3] = __expf(sc[nt][3] - mx1); sum1 += sc[nt][3];
    }
    #pragma unroll
    for (int off = 1; off < 4; off <<= 1) {
        sum0 += __shfl_xor_sync(0xffffffffu, sum0, off);
        sum1 += __shfl_xor_sync(0xffffffffu, sum1, off);
    }
    float inv0 = 1.0f / sum0, inv1 = 1.0f / sum1;
    #pragma unroll
    for (int nt = 0; nt < 8; nt++) {
        sc[nt][0] *= inv0; sc[nt][1] *= inv0;
        sc[nt][2] *= inv1; sc[nt][3] *= inv1;
    }

    // ---- O = P @ V  (64x32, K=64) ----
    float oa[4][4];
    #pragma unroll
    for (int i = 0; i < 4; i++)
        #pragma unroll
        for (int e = 0; e < 4; e++) oa[i][e] = 0.f;

    #pragma unroll
    for (int kk = 0; kk < 4; kk++) {
        unsigned ah[4], al[4];
        packsplit(sc[2 * kk][0],     sc[2 * kk][1],     ah[0], al[0]);
        packsplit(sc[2 * kk][2],     sc[2 * kk][3],     ah[1], al[1]);
        packsplit(sc[2 * kk + 1][0], sc[2 * kk + 1][1], ah[2], al[2]);
        packsplit(sc[2 * kk + 1][2], sc[2 * kk + 1][3], ah[3], al[3]);
        #pragma unroll
        for (int p2 = 0; p2 < 2; p2++) {
            unsigned bh[4], bl[4];
            unsigned vaddr = ((kk * 16 + bcol + (lane & 7)) * APAD + p2 * 16 + acol) * 2;
            ldsm4t(bh, sVh + vaddr);
            ldsm4t(bl, sVl + vaddr);
            #pragma unroll
            for (int half = 0; half < 2; half++) {
                mma16816(oa[2 * p2 + half], ah, bh + half * 2);
                mma16816(oa[2 * p2 + half], ah, bl + half * 2);
                mma16816(oa[2 * p2 + half], al, bh + half * 2);
            }
        }
    }

    // ---- store O rows < 49 as bf16 hi/lo split into g_Ahi/g_Alo ----
    #pragma unroll
    for (int nt = 0; nt < 4; nt++) {
        int n = h * HD + nt * 8 + t4 * 2;
        if (r0 < NN) {
            unsigned hw, lw;
            packsplit(oa[nt][0], oa[nt][1], hw, lw);
            size_t base = (size_t)(win * NN + r0) * CC + n;
            *(unsigned*)(g_Ahi + base) = hw;
            *(unsigned*)(g_Alo + base) = lw;
        }
        if (r1 < NN) {
            unsigned hw, lw;
            packsplit(oa[nt][2], oa[nt][3], hw, lw);
            size_t base = (size_t)(win * NN + r1) * CC + n;
            *(unsigned*)(g_Ahi + base) = hw;
            *(unsigned*)(g_Alo + base) = lw;
        }
    }
}

// ----------------------------------------------------------------
extern "C" void kernel_launch(void* const* d_in, const int* in_sizes, int n_in,
                              void* d_out, int out_size) {
    const float* x      = (const float*)d_in[0];
    const float* n1g    = (const float*)d_in[1];
    const float* n1b    = (const float*)d_in[2];
    const float* qkv_w  = (const float*)d_in[3];
    const float* qkv_b  = (const float*)d_in[4];
    const float* proj_w = (const float*)d_in[5];
    const float* proj_b = (const float*)d_in[6];
    const float* table  = (const float*)d_in[7];
    const float* n2g    = (const float*)d_in[8];
    const float* n2b    = (const float*)d_in[9];
    const float* fc1_w  = (const float*)d_in[10];
    const float* fc1_b  = (const float*)d_in[11];
    const float* fc2_w  = (const float*)d_in[12];
    const float* fc2_b  = (const float*)d_in[13];
    const int*   relidx = (const int*)d_in[14];
    float*       out    = (float*)d_out;

    float *p_win, *p_res1;
    __nv_bfloat16 *p_Ahi, *p_Alo, *p_Hhi, *p_Hlo, *p_Whi, *p_Wlo;
    cudaGetSymbolAddress((void**)&p_win,  g_win);
    cudaGetSymbolAddress((void**)&p_res1, g_res1);
    cudaGetSymbolAddress((void**)&p_Ahi,  g_Ahi);
    cudaGetSymbolAddress((void**)&p_Alo,  g_Alo);
    cudaGetSymbolAddress((void**)&p_Hhi,  g_Hhi);
    cudaGetSymbolAddress((void**)&p_Hlo,  g_Hlo);
    cudaGetSymbolAddress((void**)&p_Whi,  g_Whi);
    cudaGetSymbolAddress((void**)&p_Wlo,  g_Wlo);

    cudaFuncSetAttribute((const void*)mma_gemm<0>, cudaFuncAttributeMaxDynamicSharedMemorySize, GSMEM);
    cudaFuncSetAttribute((const void*)mma_gemm<1>, cudaFuncAttributeMaxDynamicSharedMemorySize, GSMEM);
    cudaFuncSetAttribute((const void*)mma_gemm<2>, cudaFuncAttributeMaxDynamicSharedMemorySize, GSMEM);
    cudaFuncSetAttribute((const void*)mma_gemm<3>, cudaFuncAttributeMaxDynamicSharedMemorySize, GSMEM);

    // 1) rel-pos bias gather + weight split
    bias_pre_kernel<<<(NN * NN + 127) / 128, 128>>>(table, relidx);
    split_weights<<<(W_TOT + 255) / 256, 256>>>(qkv_w, proj_w, fc1_w, fc2_w);
    // 2) LN1 + shift + window partition -> A hi/lo
    ln_shift_win_kernel<<<NTOK, 192>>>(x, n1g, n1b);
    // 3) QKV GEMM: [100352,192] x [576,192]^T -> qkv bf16 hi/lo (into g_Hhi/g_Hlo)
    mma_gemm<3><<<dim3(3 * CC / BN, NTOK / BM), 256, GSMEM>>>(
        p_Ahi, p_Alo, p_Whi + W_QKV, p_Wlo + W_QKV, qkv_b, nullptr,
        nullptr, p_Hhi, p_Hlo, 3 * CC, CC);
    // 4) windowed attention (HMMA) -> A hi/lo (attn out)
    attn_kernel<<<NWIN * HEADS, 128>>>();
    // 5) proj GEMM -> g_win fp32 (window layout)
    mma_gemm<0><<<dim3(CC / BN, NTOK / BM), 256, GSMEM>>>(
        p_Ahi, p_Alo, p_Whi + W_PROJ, p_Wlo + W_PROJ, proj_b, nullptr,
        p_win, nullptr, nullptr, CC, CC);
    // 6) window reverse + unshift + residual + LN2 -> g_res1 fp32, A hi/lo (ln2 out)
    resid_ln2_kernel<<<NTOK, 192>>>(x, n2g, n2b);
    // 7) fc1 + exact GELU -> H hi/lo
    mma_gemm<1><<<dim3(HID / BN, NTOK / BM), 256, GSMEM>>>(
        p_Ahi, p_Alo, p_Whi + W_FC1, p_Wlo + W_FC1, fc1_b, nullptr,
        nullptr, p_Hhi, p_Hlo, HID, CC);
    // 8) fc2 + residual -> d_out fp32
    mma_gemm<2><<<dim3(CC / BN, NTOK / BM), 256, GSMEM>>>(
        p_Hhi, p_Hlo, p_Whi + W_FC2, p_Wlo + W_FC2, fc2_b, p_res1,
        out, nullptr, nullptr, CC, HID);
}

// round 15
// speedup vs baseline: 3.3472x; 1.1065x over previous
#include <cuda_runtime.h>
#include <cuda_bf16.h>
#include <math.h>

#define BB   32
#define HH   56
#define WWID 56
#define CC   192
#define HEADS 6
#define HD   32
#define WS   7
#define SHIFT 3
#define HID  768
#define NTOK (BB*HH*WWID)          // 100352
#define NWIN (BB*8*8)              // 2048
#define NN   (WS*WS)               // 49

// ---------------- scratch (device globals; no allocations allowed) ----------------
__device__ float g_win [(size_t)NTOK * CC];                         // proj out fp32 (window layout)
__device__ float g_res1[(size_t)NTOK * CC];                         // x + attn branch fp32
__device__ __align__(16) __nv_bfloat16 g_Ahi[(size_t)NTOK * CC];    // A hi (ln1out/attnout/ln2out)
__device__ __align__(16) __nv_bfloat16 g_Alo[(size_t)NTOK * CC];
__device__ __align__(16) __nv_bfloat16 g_Hhi[(size_t)NTOK * HID];   // qkv hi (576) then fc1 out hi (768)
__device__ __align__(16) __nv_bfloat16 g_Hlo[(size_t)NTOK * HID];
#define W_QKV  0
#define W_PROJ 110592
#define W_FC1  147456
#define W_FC2  294912
#define W_TOT  442368
__device__ __align__(16) __nv_bfloat16 g_Whi[W_TOT];
__device__ __align__(16) __nv_bfloat16 g_Wlo[W_TOT];
__device__ float g_bias[HEADS * NN * NN];

// ---------------- helpers ----------------
__device__ __forceinline__ unsigned smem_u32(const void* p) {
    unsigned a;
    asm("{ .reg .u64 t; cvta.to.shared.u64 t, %1; cvt.u32.u64 %0, t; }" : "=r"(a) : "l"(p));
    return a;
}
__device__ __forceinline__ void cp16(unsigned dst, const void* src) {
    asm volatile("cp.async.cg.shared.global [%0], [%1], 16;" :: "r"(dst), "l"(src));
}
#define CP_COMMIT() asm volatile("cp.async.commit_group;")
#define CP_WAIT(n)  asm volatile("cp.async.wait_group %0;" :: "n"(n) : "memory")

__device__ __forceinline__ void mma16816(float* d, const unsigned* a, const unsigned* b) {
    asm volatile("mma.sync.aligned.m16n8k16.row.col.f32.bf16.bf16.f32 "
        "{%0,%1,%2,%3}, {%4,%5,%6,%7}, {%8,%9}, {%0,%1,%2,%3};"
        : "+f"(d[0]), "+f"(d[1]), "+f"(d[2]), "+f"(d[3])
        : "r"(a[0]), "r"(a[1]), "r"(a[2]), "r"(a[3]), "r"(b[0]), "r"(b[1]));
}
__device__ __forceinline__ void ldsm4(unsigned* r, unsigned a) {
    asm volatile("ldmatrix.sync.aligned.m8n8.x4.shared.b16 {%0,%1,%2,%3}, [%4];"
        : "=r"(r[0]), "=r"(r[1]), "=r"(r[2]), "=r"(r[3]) : "r"(a));
}
__device__ __forceinline__ void ldsm4t(unsigned* r, unsigned a) {
    asm volatile("ldmatrix.sync.aligned.m8n8.x4.trans.shared.b16 {%0,%1,%2,%3}, [%4];"
        : "=r"(r[0]), "=r"(r[1]), "=r"(r[2]), "=r"(r[3]) : "r"(a));
}

__device__ __forceinline__ void splitf(float v, __nv_bfloat16& h, __nv_bfloat16& l) {
    h = __float2bfloat16(v);
    l = __float2bfloat16(v - __bfloat162float(h));
}
__device__ __forceinline__ void packsplit(float x, float y, unsigned& hi, unsigned& lo) {
    __nv_bfloat16 hx = __float2bfloat16(x), hy = __float2bfloat16(y);
    float rx = x - __bfloat162float(hx), ry = y - __bfloat162float(hy);
    hi = (unsigned)__bfloat16_as_ushort(hx) | ((unsigned)__bfloat16_as_ushort(hy) << 16);
    lo = (unsigned)__bfloat16_as_ushort(__float2bfloat16(rx))
       | ((unsigned)__bfloat16_as_ushort(__float2bfloat16(ry)) << 16);
}

// ---------------- small kernels ----------------
__global__ void bias_pre_kernel(const float* __restrict__ table, const int* __restrict__ relidx) {
    int p = blockIdx.x * blockDim.x + threadIdx.x;
    if (p < NN * NN) {
        int idx = relidx[p];
        #pragma unroll
        for (int h = 0; h < HEADS; h++)
            g_bias[h * NN * NN + p] = table[idx * HEADS + h];
    }
}

__global__ void split_weights(const float* __restrict__ qkv_w, const float* __restrict__ proj_w,
                              const float* __restrict__ fc1_w, const float* __restrict__ fc2_w) {
    int i = blockIdx.x * 256 + threadIdx.x;
    if (i >= W_TOT) return;
    float v;
    if      (i < W_PROJ) v = qkv_w [i];
    else if (i < W_FC1)  v = proj_w[i - W_PROJ];
    else if (i < W_FC2)  v = fc1_w [i - W_FC1];
    else                 v = fc2_w [i - W_FC2];
    __nv_bfloat16 h, l; splitf(v, h, l);
    g_Whi[i] = h; g_Wlo[i] = l;
}

// LN1 + shift + window partition -> bf16 hi/lo.  One warp per token, 8 tokens/block.
__global__ void __launch_bounds__(256) ln_shift_win_kernel(
    const float* __restrict__ x, const float* __restrict__ g, const float* __restrict__ b) {
    int o = blockIdx.x * 8 + (threadIdx.x >> 5);
    int lane = threadIdx.x & 31;
    int win = o / NN, pos = o % NN;
    int bb = win >> 6, wi = (win >> 3) & 7, wj = win & 7;
    int i = pos / WS, j = pos % WS;
    int hs  = (wi * WS + i + SHIFT) % HH;
    int ws2 = (wj * WS + j + SHIFT) % WWID;
    const float* row = x + ((size_t)(bb * HH + hs) * WWID + ws2) * CC;
    float v[6];
    float s = 0.f, s2 = 0.f;
    #pragma unroll
    for (int q = 0; q < 6; q++) {
        v[q] = row[lane + 32 * q];
        s += v[q]; s2 += v[q] * v[q];
    }
    #pragma unroll
    for (int off = 16; off; off >>= 1) {
        s  += __shfl_xor_sync(0xffffffffu, s,  off);
        s2 += __shfl_xor_sync(0xffffffffu, s2, off);
    }
    float mu = s * (1.0f / CC);
    float var = s2 * (1.0f / CC) - mu * mu;
    float rs = rsqrtf(var + 1e-5f);
    #pragma unroll
    for (int q = 0; q < 6; q++) {
        int c = lane + 32 * q;
        float oo = (v[q] - mu) * rs * g[c] + b[c];
        __nv_bfloat16 h, l; splitf(oo, h, l);
        size_t idx = (size_t)o * CC + c;
        g_Ahi[idx] = h; g_Alo[idx] = l;
    }
}

// window reverse + unshift + residual + LN2 -> g_res1 fp32, ln2 out bf16 hi/lo. Warp per token.
__global__ void __launch_bounds__(256) resid_ln2_kernel(
    const float* __restrict__ x, const float* __restrict__ g, const float* __restrict__ b) {
    int t = blockIdx.x * 8 + (threadIdx.x >> 5);
    int lane = threadIdx.x & 31;
    int bb = t / (HH * WWID); int rem = t % (HH * WWID);
    int h = rem / WWID, w = rem % WWID;
    int h2 = (h + HH - SHIFT) % HH, w2 = (w + WWID - SHIFT) % WWID;
    int o = ((bb * 64 + (h2 / WS) * 8 + (w2 / WS)) * NN + (h2 % WS) * WS + (w2 % WS));
    const float* xr = x + (size_t)t * CC;
    const float* wr = g_win + (size_t)o * CC;
    float v[6];
    float s = 0.f, s2 = 0.f;
    #pragma unroll
    for (int q = 0; q < 6; q++) {
        int c = lane + 32 * q;
        v[q] = xr[c] + wr[c];
        g_res1[(size_t)t * CC + c] = v[q];
        s += v[q]; s2 += v[q] * v[q];
    }
    #pragma unroll
    for (int off = 16; off; off >>= 1) {
        s  += __shfl_xor_sync(0xffffffffu, s,  off);
        s2 += __shfl_xor_sync(0xffffffffu, s2, off);
    }
    float mu = s * (1.0f / CC);
    float var = s2 * (1.0f / CC) - mu * mu;
    float rs = rsqrtf(var + 1e-5f);
    #pragma unroll
    for (int q = 0; q < 6; q++) {
        int c = lane + 32 * q;
        float oo = (v[q] - mu) * rs * g[c] + b[c];
        __nv_bfloat16 hh, ll; splitf(oo, hh, ll);
        size_t idx = (size_t)t * CC + c;
        g_Ahi[idx] = hh; g_Alo[idx] = ll;
    }
}

// ---------------- mma.sync GEMM: 3-stage cp.async ring, term-reordered MMAs ----------------
#define BM 128
#define BN 96
#define BK 32
#define PADK 40                          // padded row stride (bf16): 80B, LDSM conflict-free
#define ASZ (BM * PADK * 2)              // 10240 B per A matrix tile
#define BSZ (BN * PADK * 2)              // 7680 B per B matrix tile
#define STG (2 * ASZ + 2 * BSZ)          // 35840 B per stage
#define NSTAGE 3
#define GSMEM (NSTAGE * STG)             // 107520 B

// EPI: 0 = +bias -> fp32 ; 1 = gelu(+bias) -> bf16 hi/lo ; 2 = +bias+res -> fp32 ; 3 = +bias -> bf16 hi/lo
template<int EPI>
__global__ void __launch_bounds__(256) mma_gemm(
    const __nv_bfloat16* __restrict__ Ahi, const __nv_bfloat16* __restrict__ Alo,
    const __nv_bfloat16* __restrict__ Bhi, const __nv_bfloat16* __restrict__ Blo,
    const float* __restrict__ bias, const float* __restrict__ res,
    float* __restrict__ outF, __nv_bfloat16* __restrict__ outHi, __nv_bfloat16* __restrict__ outLo,
    int N, int K)
{
    extern __shared__ __align__(16) char smem[];
    const unsigned sb = smem_u32(smem);
    const int t = threadIdx.x, wid = t >> 5, lane = t & 31;
    const int warpM = wid >> 1, warpN = wid & 1;
    const int g = lane >> 2, t4 = lane & 3;
    const int m0 = blockIdx.y * BM;
    const int n0 = blockIdx.x * BN;
    const int nchunks = K / BK;

    auto load_chunk = [&](int c, int s) {
        const int k0 = c * BK;
        const unsigned sa = sb + s * STG;
        #pragma unroll
        for (int u0 = 0; u0 < 1024; u0 += 256) {
            int u = u0 + t;
            int mat = u >> 9, r = (u >> 2) & 127, q = u & 3;
            const __nv_bfloat16* src = (mat ? Alo : Ahi) + (size_t)(m0 + r) * K + k0 + q * 8;
            cp16(sa + mat * ASZ + r * (PADK * 2) + q * 16, src);
        }
        const unsigned sbb = sa + 2 * ASZ;
        #pragma unroll
        for (int u0 = 0; u0 < 768; u0 += 256) {
            int u = u0 + t;
            int mat = (u >= 384) ? 1 : 0, uu = u - mat * 384;
            int r = uu >> 2, q = uu & 3;
            const __nv_bfloat16* src = (mat ? Blo : Bhi) + (size_t)(n0 + r) * K + k0 + q * 8;
            cp16(sbb + mat * BSZ + r * (PADK * 2) + q * 16, src);
        }
        CP_COMMIT();
    };

    float acc[2][6][4];
    #pragma unroll
    for (int i = 0; i < 2; i++)
        #pragma unroll
        for (int j = 0; j < 6; j++)
            #pragma unroll
            for (int q = 0; q < 4; q++) acc[i][j][q] = 0.f;

    const int arow = (lane & 15);
    const int acol = ((lane >> 4) << 3);
    const int brow = ((lane >> 4) << 3) + (lane & 7);
    const int bcol = ((lane >> 3) & 1) * 8;

    load_chunk(0, 0);
    if (nchunks > 1) load_chunk(1, 1);

    int stage = 0;
    for (int c = 0; c < nchunks; c++) {
        if (c + 1 < nchunks) { CP_WAIT(1); } else { CP_WAIT(0); }
        __syncthreads();
        if (c + 2 < nchunks) {
            int s2 = stage + 2; if (s2 >= NSTAGE) s2 -= NSTAGE;
            load_chunk(c + 2, s2);
        }

        const unsigned su = sb + stage * STG;

        #pragma unroll
        for (int kk = 0; kk < BK; kk += 16) {
            unsigned ah[2][4], al[2][4], bh[3][4], bl[3][4];
            #pragma unroll
            for (int mt = 0; mt < 2; mt++) {
                unsigned aaddr = su + ((warpM * 32 + mt * 16 + arow) * PADK + kk + acol) * 2;
                ldsm4(ah[mt], aaddr);
                ldsm4(al[mt], aaddr + ASZ);
            }
            #pragma unroll
            for (int p2 = 0; p2 < 3; p2++) {
                unsigned baddr = su + 2 * ASZ
                    + ((warpN * 48 + p2 * 16 + brow) * PADK + kk + bcol) * 2;
                ldsm4(bh[p2], baddr);
                ldsm4(bl[p2], baddr + BSZ);
            }
            // term-reordered: accumulator reuse distance = 12 MMAs
            #pragma unroll
            for (int mt = 0; mt < 2; mt++)
                #pragma unroll
                for (int nt = 0; nt < 6; nt++)
                    mma16816(acc[mt][nt], ah[mt], bh[nt >> 1] + (nt & 1) * 2);
            #pragma unroll
            for (int mt = 0; mt < 2; mt++)
                #pragma unroll
                for (int nt = 0; nt < 6; nt++)
                    mma16816(acc[mt][nt], ah[mt], bl[nt >> 1] + (nt & 1) * 2);
            #pragma unroll
            for (int mt = 0; mt < 2; mt++)
                #pragma unroll
                for (int nt = 0; nt < 6; nt++)
                    mma16816(acc[mt][nt], al[mt], bh[nt >> 1] + (nt & 1) * 2);
        }
        stage++; if (stage >= NSTAGE) stage -= NSTAGE;
    }

    // ---- epilogue ----
    #pragma unroll
    for (int mt = 0; mt < 2; mt++) {
        int m = m0 + warpM * 32 + mt * 16 + g;
        #pragma unroll
        for (int nt = 0; nt < 6; nt++) {
            int n = n0 + warpN * 48 + nt * 8 + t4 * 2;
            float b0 = bias[n], b1 = bias[n + 1];
            #pragma unroll
            for (int half = 0; half < 2; half++) {
                int mr = m + half * 8;
                float v0 = acc[mt][nt][2 * half]     + b0;
                float v1 = acc[mt][nt][2 * half + 1] + b1;
                size_t base = (size_t)mr * N + n;
                if (EPI == 1 || EPI == 3) {
                    if (EPI == 1) {
                        v0 = 0.5f * v0 * (1.0f + erff(v0 * 0.7071067811865476f));
                        v1 = 0.5f * v1 * (1.0f + erff(v1 * 0.7071067811865476f));
                    }
                    unsigned hw, lw;
                    packsplit(v0, v1, hw, lw);
                    *(unsigned*)(outHi + base) = hw;
                    *(unsigned*)(outLo + base) = lw;
                } else {
                    if (EPI == 2) {
                        float2 rv = *(const float2*)(res + base);
                        v0 += rv.x; v1 += rv.y;
                    }
                    *(float2*)(outF + base) = make_float2(v0, v1);
                }
            }
        }
    }
}

// ---------------- HMMA attention: one block per (window, head), 4 warps ----------------
#define APAD 40   // row stride in bf16 (80 B)
__global__ void __launch_bounds__(128) attn_kernel() {
    const int wh = blockIdx.x;
    const int win = wh / HEADS, h = wh % HEADS;
    __shared__ __align__(16) __nv_bfloat16 sT[6][64 * APAD];  // Qh,Ql,Kh,Kl,Vh,Vl
    const int t = threadIdx.x, wid = t >> 5, lane = t & 31;
    const int g = lane >> 2, t4 = lane & 3;

    for (int u = t; u < 360; u += 128) {
        int tile = u / 60, rem = u % 60;
        int rr = 49 + (rem >> 2), q4 = rem & 3;
        *(uint4*)((char*)sT[tile] + rr * (APAD * 2) + q4 * 16) = make_uint4(0, 0, 0, 0);
    }
    for (int u = t; u < 1176; u += 128) {
        int tile = u / 196, rem = u % 196;
        int rr = rem >> 2, q4 = rem & 3;
        const __nv_bfloat16* src = ((tile & 1) ? g_Hlo : g_Hhi)
            + (size_t)(win * NN + rr) * 576 + (tile >> 1) * CC + h * HD + q4 * 8;
        cp16(smem_u32((char*)sT[tile] + rr * (APAD * 2) + q4 * 16), src);
    }
    CP_COMMIT(); CP_WAIT(0);
    __syncthreads();

    const unsigned sQh = smem_u32(sT[0]), sQl = smem_u32(sT[1]);
    const unsigned sKh = smem_u32(sT[2]), sKl = smem_u32(sT[3]);
    const unsigned sVh = smem_u32(sT[4]), sVl = smem_u32(sT[5]);

    float sc[8][4];
    #pragma unroll
    for (int i = 0; i < 8; i++)
        #pragma unroll
        for (int e = 0; e < 4; e++) sc[i][e] = 0.f;

    const int arow = (lane & 15), acol = ((lane >> 4) << 3);
    const int brow = ((lane >> 4) << 3) + (lane & 7), bcol = ((lane >> 3) & 1) * 8;

    #pragma unroll
    for (int kk = 0; kk < 2; kk++) {
        unsigned ah[4], al[4];
        unsigned qaddr = ((wid * 16 + arow) * APAD + kk * 16 + acol) * 2;
        ldsm4(ah, sQh + qaddr);
        ldsm4(al, sQl + qaddr);
        #pragma unroll
        for (int p2 = 0; p2 < 4; p2++) {
            unsigned bh[4], bl[4];
            unsigned kaddr = ((p2 * 16 + brow) * APAD + kk * 16 + bcol) * 2;
            ldsm4(bh, sKh + kaddr);
            ldsm4(bl, sKl + kaddr);
            #pragma unroll
            for (int half = 0; half < 2; half++) {
                mma16816(sc[2 * p2 + half], ah, bh + half * 2);
                mma16816(sc[2 * p2 + half], ah, bl + half * 2);
                mma16816(sc[2 * p2 + half], al, bh + half * 2);
            }
        }
    }

    const int r0 = wid * 16 + g, r1 = r0 + 8;
    const float scale = 0.17677669529663687f;
    #pragma unroll
    for (int nt = 0; nt < 8; nt++) {
        #pragma unroll
        for (int e = 0; e < 4; e++) {
            int r = (e < 2) ? r0 : r1;
            int j = nt * 8 + t4 * 2 + (e & 1);
            float v = -1e30f;
            if (r < NN && j < NN)
                v = sc[nt][e] * scale + g_bias[h * NN * NN + r * NN + j];
            sc[nt][e] = v;
        }
    }
    float mx0 = -1e30f, mx1 = -1e30f;
    #pragma unroll
    for (int nt = 0; nt < 8; nt++) {
        mx0 = fmaxf(mx0, fmaxf(sc[nt][0], sc[nt][1]));
        mx1 = fmaxf(mx1, fmaxf(sc[nt][2], sc[nt][3]));
    }
    #pragma unroll
    for (int off = 1; off < 4; off <<= 1) {
        mx0 = fmaxf(mx0, __shfl_xor_sync(0xffffffffu, mx0, off));
        mx1 = fmaxf(mx1, __shfl_xor_sync(0xffffffffu, mx1, off));
    }
    float sum0 = 0.f, sum1 = 0.f;
    #pragma unroll
    for (int nt = 0; nt < 8; nt++) {
        sc[nt][0] = __expf(sc[nt][0] - mx0); sum0 += sc[nt][0];
        sc[nt][1] = __expf(sc[nt][1] - mx0); sum0 += sc[nt][1];
        sc[nt][2] = __expf(sc[nt][2] - mx1); sum1 += sc[nt][2];
        sc[nt][3] = __expf(sc[nt][3] - mx1); sum1 += sc[nt][3];
    }
    #pragma unroll
    for (int off = 1; off < 4; off <<= 1) {
        sum0 += __shfl_xor_sync(0xffffffffu, sum0, off);
        sum1 += __shfl_xor_sync(0xffffffffu, sum1, off);
    }
    float inv0 = 1.0f / sum0, inv1 = 1.0f / sum1;
    #pragma unroll
    for (int nt = 0; nt < 8; nt++) {
        sc[nt][0] *= inv0; sc[nt][1] *= inv0;
        sc[nt][2] *= inv1; sc[nt][3] *= inv1;
    }

    float oa[4][4];
    #pragma unroll
    for (int i = 0; i < 4; i++)
        #pragma unroll
        for (int e = 0; e < 4; e++) oa[i][e] = 0.f;

    #pragma unroll
    for (int kk = 0; kk < 4; kk++) {
        unsigned ah[4], al[4];
        packsplit(sc[2 * kk][0],     sc[2 * kk][1],     ah[0], al[0]);
        packsplit(sc[2 * kk][2],     sc[2 * kk][3],     ah[1], al[1]);
        packsplit(sc[2 * kk + 1][0], sc[2 * kk + 1][1], ah[2], al[2]);
        packsplit(sc[2 * kk + 1][2], sc[2 * kk + 1][3], ah[3], al[3]);
        #pragma unroll
        for (int p2 = 0; p2 < 2; p2++) {
            unsigned bh[4], bl[4];
            unsigned vaddr = ((kk * 16 + bcol + (lane & 7)) * APAD + p2 * 16 + acol) * 2;
            ldsm4t(bh, sVh + vaddr);
            ldsm4t(bl, sVl + vaddr);
            #pragma unroll
            for (int half = 0; half < 2; half++) {
                mma16816(oa[2 * p2 + half], ah, bh + half * 2);
                mma16816(oa[2 * p2 + half], ah, bl + half * 2);
                mma16816(oa[2 * p2 + half], al, bh + half * 2);
            }
        }
    }

    #pragma unroll
    for (int nt = 0; nt < 4; nt++) {
        int n = h * HD + nt * 8 + t4 * 2;
        if (r0 < NN) {
            unsigned hw, lw;
            packsplit(oa[nt][0], oa[nt][1], hw, lw);
            size_t base = (size_t)(win * NN + r0) * CC + n;
            *(unsigned*)(g_Ahi + base) = hw;
            *(unsigned*)(g_Alo + base) = lw;
        }
        if (r1 < NN) {
            unsigned hw, lw;
            packsplit(oa[nt][2], oa[nt][3], hw, lw);
            size_t base = (size_t)(win * NN + r1) * CC + n;
            *(unsigned*)(g_Ahi + base) = hw;
            *(unsigned*)(g_Alo + base) = lw;
        }
    }
}

// ----------------------------------------------------------------
extern "C" void kernel_launch(void* const* d_in, const int* in_sizes, int n_in,
                              void* d_out, int out_size) {
    const float* x      = (const float*)d_in[0];
    const float* n1g    = (const float*)d_in[1];
    const float* n1b    = (const float*)d_in[2];
    const float* qkv_w  = (const float*)d_in[3];
    const float* qkv_b  = (const float*)d_in[4];
    const float* proj_w = (const float*)d_in[5];
    const float* proj_b = (const float*)d_in[6];
    const float* table  = (const float*)d_in[7];
    const float* n2g    = (const float*)d_in[8];
    const float* n2b    = (const float*)d_in[9];
    const float* fc1_w  = (const float*)d_in[10];
    const float* fc1_b  = (const float*)d_in[11];
    const float* fc2_w  = (const float*)d_in[12];
    const float* fc2_b  = (const float*)d_in[13];
    const int*   relidx = (const int*)d_in[14];
    float*       out    = (float*)d_out;

    float *p_win, *p_res1;
    __nv_bfloat16 *p_Ahi, *p_Alo, *p_Hhi, *p_Hlo, *p_Whi, *p_Wlo;
    cudaGetSymbolAddress((void**)&p_win,  g_win);
    cudaGetSymbolAddress((void**)&p_res1, g_res1);
    cudaGetSymbolAddress((void**)&p_Ahi,  g_Ahi);
    cudaGetSymbolAddress((void**)&p_Alo,  g_Alo);
    cudaGetSymbolAddress((void**)&p_Hhi,  g_Hhi);
    cudaGetSymbolAddress((void**)&p_Hlo,  g_Hlo);
    cudaGetSymbolAddress((void**)&p_Whi,  g_Whi);
    cudaGetSymbolAddress((void**)&p_Wlo,  g_Wlo);

    cudaFuncSetAttribute((const void*)mma_gemm<0>, cudaFuncAttributeMaxDynamicSharedMemorySize, GSMEM);
    cudaFuncSetAttribute((const void*)mma_gemm<1>, cudaFuncAttributeMaxDynamicSharedMemorySize, GSMEM);
    cudaFuncSetAttribute((const void*)mma_gemm<2>, cudaFuncAttributeMaxDynamicSharedMemorySize, GSMEM);
    cudaFuncSetAttribute((const void*)mma_gemm<3>, cudaFuncAttributeMaxDynamicSharedMemorySize, GSMEM);

    // 1) rel-pos bias gather + weight split
    bias_pre_kernel<<<(NN * NN + 127) / 128, 128>>>(table, relidx);
    split_weights<<<(W_TOT + 255) / 256, 256>>>(qkv_w, proj_w, fc1_w, fc2_w);
    // 2) LN1 + shift + window partition -> A hi/lo
    ln_shift_win_kernel<<<NTOK / 8, 256>>>(x, n1g, n1b);
    // 3) QKV GEMM -> qkv bf16 hi/lo (into g_Hhi/g_Hlo)
    mma_gemm<3><<<dim3(3 * CC / BN, NTOK / BM), 256, GSMEM>>>(
        p_Ahi, p_Alo, p_Whi + W_QKV, p_Wlo + W_QKV, qkv_b, nullptr,
        nullptr, p_Hhi, p_Hlo, 3 * CC, CC);
    // 4) windowed attention (HMMA) -> A hi/lo
    attn_kernel<<<NWIN * HEADS, 128>>>();
    // 5) proj GEMM -> g_win fp32 (window layout)
    mma_gemm<0><<<dim3(CC / BN, NTOK / BM), 256, GSMEM>>>(
        p_Ahi, p_Alo, p_Whi + W_PROJ, p_Wlo + W_PROJ, proj_b, nullptr,
        p_win, nullptr, nullptr, CC, CC);
    // 6) window reverse + unshift + residual + LN2
    resid_ln2_kernel<<<NTOK / 8, 256>>>(x, n2g, n2b);
    // 7) fc1 + exact GELU -> H hi/lo
    mma_gemm<1><<<dim3(HID / BN, NTOK / BM), 256, GSMEM>>>(
        p_Ahi, p_Alo, p_Whi + W_FC1, p_Wlo + W_FC1, fc1_b, nullptr,
        nullptr, p_Hhi, p_Hlo, HID, CC);
    // 8) fc2 + residual -> d_out fp32
    mma_gemm<2><<<dim3(CC / BN, NTOK / BM), 256, GSMEM>>>(
        p_Hhi, p_Hlo, p_Whi + W_FC2, p_Wlo + W_FC2, fc2_b, p_res1,
        out, nullptr, nullptr, CC, HID);
}

// round 17
// speedup vs baseline: 3.4022x; 1.0164x over previous
#include <cuda_runtime.h>
#include <cuda_bf16.h>
#include <math.h>

#define BB   32
#define HH   56
#define WWID 56
#define CC   192
#define HEADS 6
#define HD   32
#define WS   7
#define SHIFT 3
#define HID  768
#define NTOK (BB*HH*WWID)          // 100352
#define NWIN (BB*8*8)              // 2048
#define NN   (WS*WS)               // 49

// ---------------- scratch (device globals; no allocations allowed) ----------------
__device__ float g_win [(size_t)NTOK * CC];                         // proj out fp32 (window layout)
__device__ float g_res1[(size_t)NTOK * CC];                         // x + attn branch fp32
__device__ __align__(16) __nv_bfloat16 g_Ahi[(size_t)NTOK * CC];    // A hi (ln1out/attnout/ln2out)
__device__ __align__(16) __nv_bfloat16 g_Alo[(size_t)NTOK * CC];
__device__ __align__(16) __nv_bfloat16 g_Hhi[(size_t)NTOK * HID];   // qkv hi (576) then fc1 out hi (768)
__device__ __align__(16) __nv_bfloat16 g_Hlo[(size_t)NTOK * HID];
#define W_QKV  0
#define W_PROJ 110592
#define W_FC1  147456
#define W_FC2  294912
#define W_TOT  442368
__device__ __align__(16) __nv_bfloat16 g_Whi[W_TOT];
__device__ __align__(16) __nv_bfloat16 g_Wlo[W_TOT];
__device__ float g_bias[HEADS * NN * NN];

// ---------------- helpers ----------------
__device__ __forceinline__ unsigned smem_u32(const void* p) {
    unsigned a;
    asm("{ .reg .u64 t; cvta.to.shared.u64 t, %1; cvt.u32.u64 %0, t; }" : "=r"(a) : "l"(p));
    return a;
}
__device__ __forceinline__ void cp16(unsigned dst, const void* src) {
    asm volatile("cp.async.cg.shared.global [%0], [%1], 16;" :: "r"(dst), "l"(src));
}
#define CP_COMMIT() asm volatile("cp.async.commit_group;")
#define CP_WAIT(n)  asm volatile("cp.async.wait_group %0;" :: "n"(n) : "memory")

__device__ __forceinline__ void mma16816(float* d, const unsigned* a, const unsigned* b) {
    asm volatile("mma.sync.aligned.m16n8k16.row.col.f32.bf16.bf16.f32 "
        "{%0,%1,%2,%3}, {%4,%5,%6,%7}, {%8,%9}, {%0,%1,%2,%3};"
        : "+f"(d[0]), "+f"(d[1]), "+f"(d[2]), "+f"(d[3])
        : "r"(a[0]), "r"(a[1]), "r"(a[2]), "r"(a[3]), "r"(b[0]), "r"(b[1]));
}
__device__ __forceinline__ void ldsm4(unsigned* r, unsigned a) {
    asm volatile("ldmatrix.sync.aligned.m8n8.x4.shared.b16 {%0,%1,%2,%3}, [%4];"
        : "=r"(r[0]), "=r"(r[1]), "=r"(r[2]), "=r"(r[3]) : "r"(a));
}
__device__ __forceinline__ void ldsm4t(unsigned* r, unsigned a) {
    asm volatile("ldmatrix.sync.aligned.m8n8.x4.trans.shared.b16 {%0,%1,%2,%3}, [%4];"
        : "=r"(r[0]), "=r"(r[1]), "=r"(r[2]), "=r"(r[3]) : "r"(a));
}

__device__ __forceinline__ void splitf(float v, __nv_bfloat16& h, __nv_bfloat16& l) {
    h = __float2bfloat16(v);
    l = __float2bfloat16(v - __bfloat162float(h));
}
__device__ __forceinline__ void packsplit(float x, float y, unsigned& hi, unsigned& lo) {
    __nv_bfloat16 hx = __float2bfloat16(x), hy = __float2bfloat16(y);
    float rx = x - __bfloat162float(hx), ry = y - __bfloat162float(hy);
    hi = (unsigned)__bfloat16_as_ushort(hx) | ((unsigned)__bfloat16_as_ushort(hy) << 16);
    lo = (unsigned)__bfloat16_as_ushort(__float2bfloat16(rx))
       | ((unsigned)__bfloat16_as_ushort(__float2bfloat16(ry)) << 16);
}

// ---------------- small kernels ----------------
__global__ void bias_pre_kernel(const float* __restrict__ table, const int* __restrict__ relidx) {
    int p = blockIdx.x * blockDim.x + threadIdx.x;
    if (p < NN * NN) {
        int idx = relidx[p];
        #pragma unroll
        for (int h = 0; h < HEADS; h++)
            g_bias[h * NN * NN + p] = table[idx * HEADS + h];
    }
}

__global__ void split_weights(const float* __restrict__ qkv_w, const float* __restrict__ proj_w,
                              const float* __restrict__ fc1_w, const float* __restrict__ fc2_w) {
    int i = blockIdx.x * 256 + threadIdx.x;
    if (i >= W_TOT) return;
    float v;
    if      (i < W_PROJ) v = qkv_w [i];
    else if (i < W_FC1)  v = proj_w[i - W_PROJ];
    else if (i < W_FC2)  v = fc1_w [i - W_FC1];
    else                 v = fc2_w [i - W_FC2];
    __nv_bfloat16 h, l; splitf(v, h, l);
    g_Whi[i] = h; g_Wlo[i] = l;
}

// LN1 + shift + window partition -> bf16 hi/lo.  One warp per token, 8 tokens/block.
__global__ void __launch_bounds__(256) ln_shift_win_kernel(
    const float* __restrict__ x, const float* __restrict__ g, const float* __restrict__ b) {
    int o = blockIdx.x * 8 + (threadIdx.x >> 5);
    int lane = threadIdx.x & 31;
    int win = o / NN, pos = o % NN;
    int bb = win >> 6, wi = (win >> 3) & 7, wj = win & 7;
    int i = pos / WS, j = pos % WS;
    int hs  = (wi * WS + i + SHIFT) % HH;
    int ws2 = (wj * WS + j + SHIFT) % WWID;
    const float* row = x + ((size_t)(bb * HH + hs) * WWID + ws2) * CC;
    float v[6];
    float s = 0.f, s2 = 0.f;
    #pragma unroll
    for (int q = 0; q < 6; q++) {
        v[q] = row[lane + 32 * q];
        s += v[q]; s2 += v[q] * v[q];
    }
    #pragma unroll
    for (int off = 16; off; off >>= 1) {
        s  += __shfl_xor_sync(0xffffffffu, s,  off);
        s2 += __shfl_xor_sync(0xffffffffu, s2, off);
    }
    float mu = s * (1.0f / CC);
    float var = s2 * (1.0f / CC) - mu * mu;
    float rs = rsqrtf(var + 1e-5f);
    #pragma unroll
    for (int q = 0; q < 6; q++) {
        int c = lane + 32 * q;
        float oo = (v[q] - mu) * rs * g[c] + b[c];
        __nv_bfloat16 h, l; splitf(oo, h, l);
        size_t idx = (size_t)o * CC + c;
        g_Ahi[idx] = h; g_Alo[idx] = l;
    }
}

// window reverse + unshift + residual + LN2 -> g_res1 fp32, ln2 out bf16 hi/lo. Warp per token.
__global__ void __launch_bounds__(256) resid_ln2_kernel(
    const float* __restrict__ x, const float* __restrict__ g, const float* __restrict__ b) {
    int t = blockIdx.x * 8 + (threadIdx.x >> 5);
    int lane = threadIdx.x & 31;
    int bb = t / (HH * WWID); int rem = t % (HH * WWID);
    int h = rem / WWID, w = rem % WWID;
    int h2 = (h + HH - SHIFT) % HH, w2 = (w + WWID - SHIFT) % WWID;
    int o = ((bb * 64 + (h2 / WS) * 8 + (w2 / WS)) * NN + (h2 % WS) * WS + (w2 % WS));
    const float* xr = x + (size_t)t * CC;
    const float* wr = g_win + (size_t)o * CC;
    float v[6];
    float s = 0.f, s2 = 0.f;
    #pragma unroll
    for (int q = 0; q < 6; q++) {
        int c = lane + 32 * q;
        v[q] = xr[c] + wr[c];
        g_res1[(size_t)t * CC + c] = v[q];
        s += v[q]; s2 += v[q] * v[q];
    }
    #pragma unroll
    for (int off = 16; off; off >>= 1) {
        s  += __shfl_xor_sync(0xffffffffu, s,  off);
        s2 += __shfl_xor_sync(0xffffffffu, s2, off);
    }
    float mu = s * (1.0f / CC);
    float var = s2 * (1.0f / CC) - mu * mu;
    float rs = rsqrtf(var + 1e-5f);
    #pragma unroll
    for (int q = 0; q < 6; q++) {
        int c = lane + 32 * q;
        float oo = (v[q] - mu) * rs * g[c] + b[c];
        __nv_bfloat16 hh, ll; splitf(oo, hh, ll);
        size_t idx = (size_t)t * CC + c;
        g_Ahi[idx] = hh; g_Alo[idx] = ll;
    }
}

// ---------------- mma.sync GEMM: 3-stage cp.async ring, fragment-pipelined MMAs ----------------
#define BM 128
#define BN 96
#define BK 32
#define PADK 40                          // padded row stride (bf16): 80B, LDSM conflict-free
#define ASZ (BM * PADK * 2)              // 10240 B per A matrix tile
#define BSZ (BN * PADK * 2)              // 7680 B per B matrix tile
#define STG (2 * ASZ + 2 * BSZ)          // 35840 B per stage
#define NSTAGE 3
#define GSMEM (NSTAGE * STG)             // 107520 B

// EPI: 0 = +bias -> fp32 ; 1 = gelu(+bias) -> bf16 hi/lo ; 2 = +bias+res -> fp32 ; 3 = +bias -> bf16 hi/lo
template<int EPI>
__global__ void __launch_bounds__(256, 2) mma_gemm(
    const __nv_bfloat16* __restrict__ Ahi, const __nv_bfloat16* __restrict__ Alo,
    const __nv_bfloat16* __restrict__ Bhi, const __nv_bfloat16* __restrict__ Blo,
    const float* __restrict__ bias, const float* __restrict__ res,
    float* __restrict__ outF, __nv_bfloat16* __restrict__ outHi, __nv_bfloat16* __restrict__ outLo,
    int N, int K)
{
    extern __shared__ __align__(16) char smem[];
    const unsigned sb = smem_u32(smem);
    const int t = threadIdx.x, wid = t >> 5, lane = t & 31;
    const int warpM = wid >> 1, warpN = wid & 1;
    const int g = lane >> 2, t4 = lane & 3;
    const int m0 = blockIdx.y * BM;
    const int n0 = blockIdx.x * BN;
    const int nchunks = K / BK;

    auto load_chunk = [&](int c, int s) {
        const int k0 = c * BK;
        const unsigned sa = sb + s * STG;
        #pragma unroll
        for (int u0 = 0; u0 < 1024; u0 += 256) {
            int u = u0 + t;
            int mat = u >> 9, r = (u >> 2) & 127, q = u & 3;
            const __nv_bfloat16* src = (mat ? Alo : Ahi) + (size_t)(m0 + r) * K + k0 + q * 8;
            cp16(sa + mat * ASZ + r * (PADK * 2) + q * 16, src);
        }
        const unsigned sbb = sa + 2 * ASZ;
        #pragma unroll
        for (int u0 = 0; u0 < 768; u0 += 256) {
            int u = u0 + t;
            int mat = (u >= 384) ? 1 : 0, uu = u - mat * 384;
            int r = uu >> 2, q = uu & 3;
            const __nv_bfloat16* src = (mat ? Blo : Bhi) + (size_t)(n0 + r) * K + k0 + q * 8;
            cp16(sbb + mat * BSZ + r * (PADK * 2) + q * 16, src);
        }
        CP_COMMIT();
    };

    float acc[2][6][4];
    #pragma unroll
    for (int i = 0; i < 2; i++)
        #pragma unroll
        for (int j = 0; j < 6; j++)
            #pragma unroll
            for (int q = 0; q < 4; q++) acc[i][j][q] = 0.f;

    const int arow = (lane & 15);
    const int acol = ((lane >> 4) << 3);
    const int brow = ((lane >> 4) << 3) + (lane & 7);
    const int bcol = ((lane >> 3) & 1) * 8;

    // double-buffered fragment registers
    unsigned ah[2][2][4], al[2][2][4], bh[2][3][4], bl[2][3][4];

    load_chunk(0, 0);
    if (nchunks > 1) load_chunk(1, 1);

    int stage = 0;
    for (int c = 0; c < nchunks; c++) {
        if (c + 1 < nchunks) { CP_WAIT(1); } else { CP_WAIT(0); }
        __syncthreads();
        if (c + 2 < nchunks) {
            int s2 = stage + 2; if (s2 >= NSTAGE) s2 -= NSTAGE;
            load_chunk(c + 2, s2);
        }

        const unsigned su = sb + stage * STG;

        // preload fragments for kk=0 into buffer 0
        #pragma unroll
        for (int mt = 0; mt < 2; mt++) {
            unsigned aaddr = su + ((warpM * 32 + mt * 16 + arow) * PADK + acol) * 2;
            ldsm4(ah[0][mt], aaddr);
            ldsm4(al[0][mt], aaddr + ASZ);
        }
        #pragma unroll
        for (int p2 = 0; p2 < 3; p2++) {
            unsigned baddr = su + 2 * ASZ + ((warpN * 48 + p2 * 16 + brow) * PADK + bcol) * 2;
            ldsm4(bh[0][p2], baddr);
            ldsm4(bl[0][p2], baddr + BSZ);
        }

        #pragma unroll
        for (int kk = 0; kk < BK; kk += 16) {
            const int u = (kk >> 4) & 1, nu = u ^ 1;
            const bool more = (kk + 16) < BK;
            // group 1: Ah*Bh
            #pragma unroll
            for (int mt = 0; mt < 2; mt++)
                #pragma unroll
                for (int nt = 0; nt < 6; nt++)
                    mma16816(acc[mt][nt], ah[u][mt], bh[u][nt >> 1] + (nt & 1) * 2);
            // prefetch next slab's A fragments
            if (more) {
                #pragma unroll
                for (int mt = 0; mt < 2; mt++) {
                    unsigned aaddr = su + ((warpM * 32 + mt * 16 + arow) * PADK + kk + 16 + acol) * 2;
                    ldsm4(ah[nu][mt], aaddr);
                    ldsm4(al[nu][mt], aaddr + ASZ);
                }
            }
            // group 2: Ah*Bl  (bl[u] dies after this)
            #pragma unroll
            for (int mt = 0; mt < 2; mt++)
                #pragma unroll
                for (int nt = 0; nt < 6; nt++)
                    mma16816(acc[mt][nt], ah[u][mt], bl[u][nt >> 1] + (nt & 1) * 2);
            // prefetch next slab's B fragments
            if (more) {
                #pragma unroll
                for (int p2 = 0; p2 < 3; p2++) {
                    unsigned baddr = su + 2 * ASZ
                        + ((warpN * 48 + p2 * 16 + brow) * PADK + kk + 16 + bcol) * 2;
                    ldsm4(bh[nu][p2], baddr);
                    ldsm4(bl[nu][p2], baddr + BSZ);
                }
            }
            // group 3: Al*Bh
            #pragma unroll
            for (int mt = 0; mt < 2; mt++)
                #pragma unroll
                for (int nt = 0; nt < 6; nt++)
                    mma16816(acc[mt][nt], al[u][mt], bh[u][nt >> 1] + (nt & 1) * 2);
        }
        stage++; if (stage >= NSTAGE) stage -= NSTAGE;
    }

    // ---- epilogue ----
    #pragma unroll
    for (int mt = 0; mt < 2; mt++) {
        int m = m0 + warpM * 32 + mt * 16 + g;
        #pragma unroll
        for (int nt = 0; nt < 6; nt++) {
            int n = n0 + warpN * 48 + nt * 8 + t4 * 2;
            float b0 = bias[n], b1 = bias[n + 1];
            #pragma unroll
            for (int half = 0; half < 2; half++) {
                int mr = m + half * 8;
                float v0 = acc[mt][nt][2 * half]     + b0;
                float v1 = acc[mt][nt][2 * half + 1] + b1;
                size_t base = (size_t)mr * N + n;
                if (EPI == 1 || EPI == 3) {
                    if (EPI == 1) {
                        v0 = 0.5f * v0 * (1.0f + erff(v0 * 0.7071067811865476f));
                        v1 = 0.5f * v1 * (1.0f + erff(v1 * 0.7071067811865476f));
                    }
                    unsigned hw, lw;
                    packsplit(v0, v1, hw, lw);
                    *(unsigned*)(outHi + base) = hw;
                    *(unsigned*)(outLo + base) = lw;
                } else {
                    if (EPI == 2) {
                        float2 rv = *(const float2*)(res + base);
                        v0 += rv.x; v1 += rv.y;
                    }
                    *(float2*)(outF + base) = make_float2(v0, v1);
                }
            }
        }
    }
}

// ---------------- HMMA attention: one block per (window, head), 4 warps ----------------
#define APAD 40   // row stride in bf16 (80 B)
__global__ void __launch_bounds__(128) attn_kernel() {
    const int wh = blockIdx.x;
    const int win = wh / HEADS, h = wh % HEADS;
    __shared__ __align__(16) __nv_bfloat16 sT[6][64 * APAD];  // Qh,Ql,Kh,Kl,Vh,Vl
    const int t = threadIdx.x, wid = t >> 5, lane = t & 31;
    const int g = lane >> 2, t4 = lane & 3;

    for (int u = t; u < 360; u += 128) {
        int tile = u / 60, rem = u % 60;
        int rr = 49 + (rem >> 2), q4 = rem & 3;
        *(uint4*)((char*)sT[tile] + rr * (APAD * 2) + q4 * 16) = make_uint4(0, 0, 0, 0);
    }
    for (int u = t; u < 1176; u += 128) {
        int tile = u / 196, rem = u % 196;
        int rr = rem >> 2, q4 = rem & 3;
        const __nv_bfloat16* src = ((tile & 1) ? g_Hlo : g_Hhi)
            + (size_t)(win * NN + rr) * 576 + (tile >> 1) * CC + h * HD + q4 * 8;
        cp16(smem_u32((char*)sT[tile] + rr * (APAD * 2) + q4 * 16), src);
    }
    CP_COMMIT(); CP_WAIT(0);
    __syncthreads();

    const unsigned sQh = smem_u32(sT[0]), sQl = smem_u32(sT[1]);
    const unsigned sKh = smem_u32(sT[2]), sKl = smem_u32(sT[3]);
    const unsigned sVh = smem_u32(sT[4]), sVl = smem_u32(sT[5]);

    float sc[8][4];
    #pragma unroll
    for (int i = 0; i < 8; i++)
        #pragma unroll
        for (int e = 0; e < 4; e++) sc[i][e] = 0.f;

    const int arow = (lane & 15), acol = ((lane >> 4) << 3);
    const int brow = ((lane >> 4) << 3) + (lane & 7), bcol = ((lane >> 3) & 1) * 8;

    #pragma unroll
    for (int kk = 0; kk < 2; kk++) {
        unsigned ah[4], al[4];
        unsigned qaddr = ((wid * 16 + arow) * APAD + kk * 16 + acol) * 2;
        ldsm4(ah, sQh + qaddr);
        ldsm4(al, sQl + qaddr);
        #pragma unroll
        for (int p2 = 0; p2 < 4; p2++) {
            unsigned bh[4], bl[4];
            unsigned kaddr = ((p2 * 16 + brow) * APAD + kk * 16 + bcol) * 2;
            ldsm4(bh, sKh + kaddr);
            ldsm4(bl, sKl + kaddr);
            #pragma unroll
            for (int half = 0; half < 2; half++) {
                mma16816(sc[2 * p2 + half], ah, bh + half * 2);
                mma16816(sc[2 * p2 + half], ah, bl + half * 2);
                mma16816(sc[2 * p2 + half], al, bh + half * 2);
            }
        }
    }

    const int r0 = wid * 16 + g, r1 = r0 + 8;
    const float scale = 0.17677669529663687f;
    #pragma unroll
    for (int nt = 0; nt < 8; nt++) {
        #pragma unroll
        for (int e = 0; e < 4; e++) {
            int r = (e < 2) ? r0 : r1;
            int j = nt * 8 + t4 * 2 + (e & 1);
            float v = -1e30f;
            if (r < NN && j < NN)
                v = sc[nt][e] * scale + g_bias[h * NN * NN + r * NN + j];
            sc[nt][e] = v;
        }
    }
    float mx0 = -1e30f, mx1 = -1e30f;
    #pragma unroll
    for (int nt = 0; nt < 8; nt++) {
        mx0 = fmaxf(mx0, fmaxf(sc[nt][0], sc[nt][1]));
        mx1 = fmaxf(mx1, fmaxf(sc[nt][2], sc[nt][3]));
    }
    #pragma unroll
    for (int off = 1; off < 4; off <<= 1) {
        mx0 = fmaxf(mx0, __shfl_xor_sync(0xffffffffu, mx0, off));
        mx1 = fmaxf(mx1, __shfl_xor_sync(0xffffffffu, mx1, off));
    }
    float sum0 = 0.f, sum1 = 0.f;
    #pragma unroll
    for (int nt = 0; nt < 8; nt++) {
        sc[nt][0] = __expf(sc[nt][0] - mx0); sum0 += sc[nt][0];
        sc[nt][1] = __expf(sc[nt][1] - mx0); sum0 += sc[nt][1];
        sc[nt][2] = __expf(sc[nt][2] - mx1); sum1 += sc[nt][2];
        sc[nt][3] = __expf(sc[nt][3] - mx1); sum1 += sc[nt][3];
    }
    #pragma unroll
    for (int off = 1; off < 4; off <<= 1) {
        sum0 += __shfl_xor_sync(0xffffffffu, sum0, off);
        sum1 += __shfl_xor_sync(0xffffffffu, sum1, off);
    }
    float inv0 = 1.0f / sum0, inv1 = 1.0f / sum1;
    #pragma unroll
    for (int nt = 0; nt < 8; nt++) {
        sc[nt][0] *= inv0; sc[nt][1] *= inv0;
        sc[nt][2] *= inv1; sc[nt][3] *= inv1;
    }

    float oa[4][4];
    #pragma unroll
    for (int i = 0; i < 4; i++)
        #pragma unroll
        for (int e = 0; e < 4; e++) oa[i][e] = 0.f;

    #pragma unroll
    for (int kk = 0; kk < 4; kk++) {
        unsigned ah[4], al[4];
        packsplit(sc[2 * kk][0],     sc[2 * kk][1],     ah[0], al[0]);
        packsplit(sc[2 * kk][2],     sc[2 * kk][3],     ah[1], al[1]);
        packsplit(sc[2 * kk + 1][0], sc[2 * kk + 1][1], ah[2], al[2]);
        packsplit(sc[2 * kk + 1][2], sc[2 * kk + 1][3], ah[3], al[3]);
        #pragma unroll
        for (int p2 = 0; p2 < 2; p2++) {
            unsigned bh[4], bl[4];
            unsigned vaddr = ((kk * 16 + bcol + (lane & 7)) * APAD + p2 * 16 + acol) * 2;
            ldsm4t(bh, sVh + vaddr);
            ldsm4t(bl, sVl + vaddr);
            #pragma unroll
            for (int half = 0; half < 2; half++) {
                mma16816(oa[2 * p2 + half], ah, bh + half * 2);
                mma16816(oa[2 * p2 + half], ah, bl + half * 2);
                mma16816(oa[2 * p2 + half], al, bh + half * 2);
            }
        }
    }

    #pragma unroll
    for (int nt = 0; nt < 4; nt++) {
        int n = h * HD + nt * 8 + t4 * 2;
        if (r0 < NN) {
            unsigned hw, lw;
            packsplit(oa[nt][0], oa[nt][1], hw, lw);
            size_t base = (size_t)(win * NN + r0) * CC + n;
            *(unsigned*)(g_Ahi + base) = hw;
            *(unsigned*)(g_Alo + base) = lw;
        }
        if (r1 < NN) {
            unsigned hw, lw;
            packsplit(oa[nt][2], oa[nt][3], hw, lw);
            size_t base = (size_t)(win * NN + r1) * CC + n;
            *(unsigned*)(g_Ahi + base) = hw;
            *(unsigned*)(g_Alo + base) = lw;
        }
    }
}

// ----------------------------------------------------------------
extern "C" void kernel_launch(void* const* d_in, const int* in_sizes, int n_in,
                              void* d_out, int out_size) {
    const float* x      = (const float*)d_in[0];
    const float* n1g    = (const float*)d_in[1];
    const float* n1b    = (const float*)d_in[2];
    const float* qkv_w  = (const float*)d_in[3];
    const float* qkv_b  = (const float*)d_in[4];
    const float* proj_w = (const float*)d_in[5];
    const float* proj_b = (const float*)d_in[6];
    const float* table  = (const float*)d_in[7];
    const float* n2g    = (const float*)d_in[8];
    const float* n2b    = (const float*)d_in[9];
    const float* fc1_w  = (const float*)d_in[10];
    const float* fc1_b  = (const float*)d_in[11];
    const float* fc2_w  = (const float*)d_in[12];
    const float* fc2_b  = (const float*)d_in[13];
    const int*   relidx = (const int*)d_in[14];
    float*       out    = (float*)d_out;

    float *p_win, *p_res1;
    __nv_bfloat16 *p_Ahi, *p_Alo, *p_Hhi, *p_Hlo, *p_Whi, *p_Wlo;
    cudaGetSymbolAddress((void**)&p_win,  g_win);
    cudaGetSymbolAddress((void**)&p_res1, g_res1);
    cudaGetSymbolAddress((void**)&p_Ahi,  g_Ahi);
    cudaGetSymbolAddress((void**)&p_Alo,  g_Alo);
    cudaGetSymbolAddress((void**)&p_Hhi,  g_Hhi);
    cudaGetSymbolAddress((void**)&p_Hlo,  g_Hlo);
    cudaGetSymbolAddress((void**)&p_Whi,  g_Whi);
    cudaGetSymbolAddress((void**)&p_Wlo,  g_Wlo);

    cudaFuncSetAttribute((const void*)mma_gemm<0>, cudaFuncAttributeMaxDynamicSharedMemorySize, GSMEM);
    cudaFuncSetAttribute((const void*)mma_gemm<1>, cudaFuncAttributeMaxDynamicSharedMemorySize, GSMEM);
    cudaFuncSetAttribute((const void*)mma_gemm<2>, cudaFuncAttributeMaxDynamicSharedMemorySize, GSMEM);
    cudaFuncSetAttribute((const void*)mma_gemm<3>, cudaFuncAttributeMaxDynamicSharedMemorySize, GSMEM);

    // 1) rel-pos bias gather + weight split
    bias_pre_kernel<<<(NN * NN + 127) / 128, 128>>>(table, relidx);
    split_weights<<<(W_TOT + 255) / 256, 256>>>(qkv_w, proj_w, fc1_w, fc2_w);
    // 2) LN1 + shift + window partition -> A hi/lo
    ln_shift_win_kernel<<<NTOK / 8, 256>>>(x, n1g, n1b);
    // 3) QKV GEMM -> qkv bf16 hi/lo (into g_Hhi/g_Hlo)
    mma_gemm<3><<<dim3(3 * CC / BN, NTOK / BM), 256, GSMEM>>>(
        p_Ahi, p_Alo, p_Whi + W_QKV, p_Wlo + W_QKV, qkv_b, nullptr,
        nullptr, p_Hhi, p_Hlo, 3 * CC, CC);
    // 4) windowed attention (HMMA) -> A hi/lo
    attn_kernel<<<NWIN * HEADS, 128>>>();
    // 5) proj GEMM -> g_win fp32 (window layout)
    mma_gemm<0><<<dim3(CC / BN, NTOK / BM), 256, GSMEM>>>(
        p_Ahi, p_Alo, p_Whi + W_PROJ, p_Wlo + W_PROJ, proj_b, nullptr,
        p_win, nullptr, nullptr, CC, CC);
    // 6) window reverse + unshift + residual + LN2
    resid_ln2_kernel<<<NTOK / 8, 256>>>(x, n2g, n2b);
    // 7) fc1 + exact GELU -> H hi/lo
    mma_gemm<1><<<dim3(HID / BN, NTOK / BM), 256, GSMEM>>>(
        p_Ahi, p_Alo, p_Whi + W_FC1, p_Wlo + W_FC1, fc1_b, nullptr,
        nullptr, p_Hhi, p_Hlo, HID, CC);
    // 8) fc2 + residual -> d_out fp32
    mma_gemm<2><<<dim3(CC / BN, NTOK / BM), 256, GSMEM>>>(
        p_Hhi, p_Hlo, p_Whi + W_FC2, p_Wlo + W_FC2, fc2_b, p_res1,
        out, nullptr, nullptr, CC, HID);
}